// round 1
// baseline (speedup 1.0000x reference)
#include <cuda_runtime.h>
#include <math.h>

// Problem constants (fixed by the dataset)
#define RR     32           // rows
#define BB     64           // batch
#define CCOL   32           // cols
#define LLEN   63           // diagonal steps = R + C - 1
#define HH     256          // hidden
#define MTOT   2048         // R * B
#define F0     520          // layer-0 K: 2H + I
#define F1     1024         // layer-1 K: 2H + 2H
#define NGATE  6

// d_out layout: [output_all (2048*63*512)] [hidden_row_all (64*2*32*256)] [hidden_col_all (...)]
#define OFF1   66060288ull
#define OFF2   67108864ull

// Scratch (allocation-free rule: __device__ globals)
__device__ float g_hrow[2][MTOT * HH];
__device__ float g_hcol[2][MTOT * HH];
__device__ float g_mid[(size_t)MTOT * LLEN * (2 * HH)];   // layer-0 outputs = layer-1 inputs

typedef unsigned long long ull;

__device__ __forceinline__ ull pack2(float lo, float hi) {
    ull r; asm("mov.b64 %0, {%1,%2};" : "=l"(r) : "f"(lo), "f"(hi)); return r;
}
__device__ __forceinline__ void fma2(ull& d, ull a, ull b) {
    asm("fma.rn.f32x2 %0, %1, %2, %0;" : "+l"(d) : "l"(a), "l"(b));
}
__device__ __forceinline__ float2 unpack2(ull v) {
    float lo, hi; asm("mov.b64 {%0,%1}, %2;" : "=f"(lo), "=f"(hi) : "l"(v));
    return make_float2(lo, hi);
}
__device__ __forceinline__ float sigmoidf_(float x) {
    return 1.0f / (1.0f + __expf(-x));
}

// Load a 4-aligned chunk of z[M, k..k+3]. z = [h_row (256) | h_col (256) | x (feat)].
// Chunks never straddle region boundaries (256/512 are 4-aligned, F is 4-aligned).
__device__ __forceinline__ float4 load_z4(
    int layer, int t, int M, int k, int F,
    const float* __restrict__ inp,
    const float* __restrict__ hrow_r,
    const float* __restrict__ hcol_r)
{
    if (k >= F) return make_float4(0.f, 0.f, 0.f, 0.f);
    if (k < HH)     return *(const float4*)&hrow_r[(size_t)M * HH + k];
    if (k < 2 * HH) return *(const float4*)&hcol_r[(size_t)M * HH + (k - HH)];
    int kx = k - 2 * HH;
    if (layer == 0) {
        int r = M >> 6, b = M & 63;
        int c = t - r;                       // diagonal skew: a[r,b,t,:] = x[r,b,t-r,:]
        if (c < 0 || c >= CCOL) return make_float4(0.f, 0.f, 0.f, 0.f);
        return *(const float4*)&inp[(((size_t)b * RR + r) * CCOL + c) * 8 + kx];
    } else {
        return *(const float4*)&g_mid[((size_t)M * LLEN + t) * (2 * HH) + kx];
    }
}

// One recurrence step: gate GEMM (M=2048, 6x256 gates, K=F) fused with the
// pointwise update, state double-buffer write (roll folded into index), and
// output / hidden scatter.
// Tiling: BM=64 (m), BJ=32 (j), BK=16. 256 threads; thread = 4 m x 2 j x 6 gates,
// accumulated as f32x2 pairs over j -> FFMA2 inner loop.
__global__ __launch_bounds__(256) void step_kernel(
    int layer, int t, int rb,
    const float* __restrict__ W,      // [6H, F] row-major
    const float* __restrict__ Bias,   // [6H] (layer slice)
    const float* __restrict__ inp,    // original input (B,R,C,I)
    float* __restrict__ dout,         // harness output buffer
    int F)
{
    constexpr int BM = 64, BJ = 32, BK = 16;
    __shared__ float As[BK][BM + 4];
    __shared__ float Bs[NGATE][BK][BJ + 2];

    const int tid = threadIdx.x;
    const int m0b = blockIdx.x * BM;
    const int jb  = blockIdx.y * BJ;

    const float* hrow_r = g_hrow[rb];
    const float* hcol_r = g_hcol[rb];
    float* hrow_w = g_hrow[rb ^ 1];
    float* hcol_w = g_hcol[rb ^ 1];
    float* outp = (layer == 0) ? g_mid : dout;

    // j fast within warp -> coalesced 128B stores in epilogue
    const int tj = tid & 15;
    const int tm = tid >> 4;
    const int m0 = tm * 4;
    const int j0 = tj * 2;

    ull acc[NGATE][4];
#pragma unroll
    for (int g = 0; g < NGATE; ++g)
#pragma unroll
        for (int i = 0; i < 4; ++i) acc[g][i] = 0ull;   // bits of (0.f, 0.f)

    for (int k0 = 0; k0 < F; k0 += BK) {
        // --- load A tile: 64 m x 16 k = 256 float4, one per thread ---
        {
            int m  = tid >> 2;
            int kq = (tid & 3) * 4;
            float4 v = load_z4(layer, t, m0b + m, k0 + kq, F, inp, hrow_r, hcol_r);
            As[kq + 0][m] = v.x; As[kq + 1][m] = v.y;
            As[kq + 2][m] = v.z; As[kq + 3][m] = v.w;
        }
        // --- load B tile: 6 gates x 32 j x 16 k = 768 float4, three per thread ---
#pragma unroll
        for (int e = 0; e < 3; ++e) {
            int li = e * 256 + tid;           // float4 index in [0,768)
            int g  = li >> 7;
            int rv = li & 127;
            int j  = rv >> 2;
            int kq = (rv & 3) * 4;
            int k  = k0 + kq;
            float4 v = (k < F) ? *(const float4*)&W[(size_t)(g * HH + jb + j) * F + k]
                               : make_float4(0.f, 0.f, 0.f, 0.f);
            Bs[g][kq + 0][j] = v.x; Bs[g][kq + 1][j] = v.y;
            Bs[g][kq + 2][j] = v.z; Bs[g][kq + 3][j] = v.w;
        }
        __syncthreads();

#pragma unroll
        for (int kk = 0; kk < BK; ++kk) {
            float4 av = *(const float4*)&As[kk][m0];
            ull a2[4] = { pack2(av.x, av.x), pack2(av.y, av.y),
                          pack2(av.z, av.z), pack2(av.w, av.w) };
#pragma unroll
            for (int g = 0; g < NGATE; ++g) {
                ull b2 = *(const ull*)&Bs[g][kk][j0];
                fma2(acc[g][0], a2[0], b2);
                fma2(acc[g][1], a2[1], b2);
                fma2(acc[g][2], a2[2], b2);
                fma2(acc[g][3], a2[3], b2);
            }
        }
        __syncthreads();
    }

    // --- epilogue: bias (masked), activations, state update, scatter ---
    const int jg0 = jb + j0;
#pragma unroll
    for (int i = 0; i < 4; ++i) {
        int M = m0b + m0 + i;
        int r = M >> 6, b = M & 63;
        bool addb = (r <= t) && (t < RR);    // reference mask semantics
        float2 G[NGATE];
#pragma unroll
        for (int g = 0; g < NGATE; ++g) {
            G[g] = unpack2(acc[g][i]);
            if (addb) {
                G[g].x += Bias[g * HH + jg0];
                G[g].y += Bias[g * HH + jg0 + 1];
            }
        }
#pragma unroll
        for (int jj = 0; jj < 2; ++jj) {
            int jg = jg0 + jj;
            float v0 = jj ? G[0].y : G[0].x;
            float v1 = jj ? G[1].y : G[1].x;
            float v2 = jj ? G[2].y : G[2].x;
            float v3 = jj ? G[3].y : G[3].x;
            float v4 = jj ? G[4].y : G[4].x;
            float v5 = jj ? G[5].y : G[5].x;
            float ur = sigmoidf_(v0);
            float orr = sigmoidf_(v1);
            float uc = sigmoidf_(v2);
            float oc = sigmoidf_(v3);
            float ir = tanhf(v4);
            float ic = tanhf(v5);
            size_t hidx = (size_t)M * HH + jg;
            float hro = hrow_r[hidx];
            float hco = hcol_r[hidx];
            float hr = tanhf((1.0f - ur) * hro + ur * ir) * orr;
            float hc = tanhf((1.0f - uc) * hco + uc * ic) * oc;

            hrow_w[hidx] = hr;
            // roll(h_col, +1, axis=0): next step's slot r+1 gets this row's value
            int Mr = (((r + 1) & 31) << 6) | b;
            hcol_w[(size_t)Mr * HH + jg] = hc;

            size_t ob = ((size_t)M * LLEN + t) * (2 * HH);
            outp[ob + jg] = hr;
            outp[ob + HH + jg] = hc;

            if (t >= RR - 1) {
                int k = t - (RR - 1);
                // hidden_row_all[b, layer, k, j] : saved when this row finishes
                if (r == k)
                    dout[OFF1 + (((size_t)b * 2 + layer) * RR + k) * HH + jg] = hr;
                // hidden_col_all[b, layer, k, j] : h_col[R-1] pre-roll
                if (r == RR - 1)
                    dout[OFF2 + (((size_t)b * 2 + layer) * RR + k) * HH + jg] = hc;
            }
        }
    }
}

__global__ void zero_h_kernel() {
    int idx = blockIdx.x * blockDim.x + threadIdx.x;
    if (idx < MTOT * HH) {
        g_hrow[0][idx] = 0.f;
        g_hcol[0][idx] = 0.f;
    }
}

extern "C" void kernel_launch(void* const* d_in, const int* in_sizes, int n_in,
                              void* d_out, int out_size) {
    (void)in_sizes; (void)n_in; (void)out_size;
    const float* inp  = (const float*)d_in[0];   // (64,32,32,8)
    const float* Wf   = (const float*)d_in[1];   // (1536,520)
    const float* Wo   = (const float*)d_in[2];   // (1,1536,1024)
    const float* Bias = (const float*)d_in[3];   // (2,1536)
    float* out = (float*)d_out;

    dim3 grid(MTOT / 64, HH / 32);   // 32 x 8 = 256 blocks
    dim3 blk(256);
    int zgrid = (MTOT * HH + 255) / 256;

    // layer 0
    zero_h_kernel<<<zgrid, 256>>>();
    for (int t = 0; t < LLEN; ++t)
        step_kernel<<<grid, blk>>>(0, t, t & 1, Wf, Bias, inp, out, F0);

    // layer 1
    zero_h_kernel<<<zgrid, 256>>>();
    for (int t = 0; t < LLEN; ++t)
        step_kernel<<<grid, blk>>>(1, t, t & 1, Wo, Bias + NGATE * HH, inp, out, F1);
}

// round 3
// speedup vs baseline: 2.2902x; 2.2902x over previous
#include <cuda_runtime.h>
#include <cuda_bf16.h>
#include <math.h>
#include <stdint.h>

// ---------------- problem constants ----------------
#define RR    32
#define LLEN  63
#define HH    256
#define MTOT  2048
#define NG    6
#define KH    512            // sequential K (h_row 256 + h_col 256)
#define NTOT  1536
#define OFF1  66060288ull
#define OFF2  67108864ull

// ---------------- device scratch ----------------
__device__ float g_hrow[2][MTOT * HH];
__device__ float g_hcol[2][MTOT * HH];
__device__ __nv_bfloat16 g_zh_hi[2][MTOT * KH];
__device__ __nv_bfloat16 g_zh_lo[2][MTOT * KH];
__device__ __nv_bfloat16 g_x1_hi[(size_t)LLEN * MTOT * KH];
__device__ __nv_bfloat16 g_x1_lo[(size_t)LLEN * MTOT * KH];
__device__ __nv_bfloat16 g_wh_hi[2][NTOT * KH];
__device__ __nv_bfloat16 g_wh_lo[2][NTOT * KH];
__device__ __nv_bfloat16 g_wx_hi[NTOT * KH];
__device__ __nv_bfloat16 g_wx_lo[NTOT * KH];
__device__ float g_gx[(size_t)LLEN * MTOT * NTOT];   // per-step x-contribution of gates

// ---------------- helpers ----------------
__device__ __forceinline__ uint32_t smem_u32(const void* p) {
    uint32_t a;
    asm("{ .reg .u64 t; cvta.to.shared.u64 t, %1; cvt.u32.u64 %0, t; }" : "=r"(a) : "l"(p));
    return a;
}
__device__ __forceinline__ void cp16(uint32_t s, const void* g) {
    asm volatile("cp.async.cg.shared.global [%0], [%1], 16;" :: "r"(s), "l"(g));
}
#define CP_COMMIT() asm volatile("cp.async.commit_group;")
#define CP_WAIT1()  asm volatile("cp.async.wait_group 1;")
#define CP_WAIT0()  asm volatile("cp.async.wait_group 0;")

#define MMA(accp, a, b0, b1) \
    asm volatile("mma.sync.aligned.m16n8k16.row.col.f32.bf16.bf16.f32 " \
        "{%0,%1,%2,%3}, {%4,%5,%6,%7}, {%8,%9}, {%0,%1,%2,%3};" \
        : "+f"((accp)[0]), "+f"((accp)[1]), "+f"((accp)[2]), "+f"((accp)[3]) \
        : "r"((a)[0]), "r"((a)[1]), "r"((a)[2]), "r"((a)[3]), "r"(b0), "r"(b1))

__device__ __forceinline__ float sigmoidf_(float x) { return 1.0f / (1.0f + __expf(-x)); }
__device__ __forceinline__ uint32_t bfpack(float x, float y) {
    __nv_bfloat162 p = __floats2bfloat162_rn(x, y);
    return *reinterpret_cast<uint32_t*>(&p);
}

// ---------------- smem layout (per stage) ----------------
// rows padded to 80B (32 bf16 data + 8 pad) -> conflict-free ldS/cp.async
#define BM 128
#define BJ 32                  // j per CTA (x6 gates = 192 N-rows)
#define S_AH 0                 // A hi: 128 rows x 80B = 10240
#define S_AL 10240
#define S_BH 20480             // B hi: 192 rows x 80B = 15360
#define S_BL 35840
#define STAGE 51200
#define SMEMT (2 * STAGE)      // 102400

// ---------------- prep kernels ----------------
__global__ void prep_w(const float* __restrict__ Wf, const float* __restrict__ Wo) {
    const int N = NTOT * KH;
    for (int i = blockIdx.x * blockDim.x + threadIdx.x; i < 3 * N; i += gridDim.x * blockDim.x) {
        int rgn = i / N, j = i % N;
        int n = j / KH, k = j % KH;
        float v;
        __nv_bfloat16 *dh, *dl;
        if (rgn == 0)      { v = Wf[(size_t)n * 520 + k];        dh = g_wh_hi[0]; dl = g_wh_lo[0]; }
        else if (rgn == 1) { v = Wo[(size_t)n * 1024 + k];       dh = g_wh_hi[1]; dl = g_wh_lo[1]; }
        else               { v = Wo[(size_t)n * 1024 + 512 + k]; dh = g_wx_hi;    dl = g_wx_lo;    }
        __nv_bfloat16 hi = __float2bfloat16(v);
        dh[j] = hi;
        dl[j] = __float2bfloat16(v - __bfloat162float(hi));
    }
}

// layer-0 x-contribution: g_gx[t,M,n] = sum_{k<8} x0(t,M,k) * Wf[n][512+k]  (exact fp32)
__global__ void gx0_kernel(const float* __restrict__ inp, const float* __restrict__ Wf) {
    const int blk = blockIdx.x;                 // t*2048 + M
    const int t = blk >> 11, M = blk & (MTOT - 1);
    const int r = M >> 6, b = M & 63, c = t - r;
    const bool valid = (c >= 0 && c < 32);
    float x[8];
    if (valid) {
#pragma unroll
        for (int k = 0; k < 8; ++k)
            x[k] = inp[(((size_t)b * RR + r) * 32 + c) * 8 + k];
    }
    float* dst = g_gx + (size_t)blk * NTOT;
    for (int n = threadIdx.x; n < NTOT; n += blockDim.x) {
        float s = 0.0f;
        if (valid) {
            const float* w = Wf + (size_t)n * 520 + 512;
#pragma unroll
            for (int k = 0; k < 8; ++k) s += x[k] * w[k];
        }
        dst[n] = s;
    }
}

__global__ void init_h() {
    int i = blockIdx.x * blockDim.x + threadIdx.x;
    if (i < MTOT * KH) {
        g_zh_hi[0][i] = __float2bfloat16(0.0f);
        g_zh_lo[0][i] = __float2bfloat16(0.0f);
        if (i < MTOT * HH) { g_hrow[0][i] = 0.0f; g_hcol[0][i] = 0.0f; }
    }
}

// ---------------- fused GEMM (+ pointwise epilogue in SEQ mode) ----------------
// mode 0 (SEQ):   D = zh[par] @ Wh[layer]^T + g_gx[t] (+bias) -> pointwise update
// mode 1 (BATCH): g_gx[t] = X1[t] @ Wx^T   (t = blockIdx.z)
__global__ __launch_bounds__(256, 1) void gemm_k(
    int mode, int layer, int t_, int par,
    const float* __restrict__ Bias, float* __restrict__ dout)
{
    extern __shared__ char sm[];
    const uint32_t sbase = smem_u32(sm);
    const int tid = threadIdx.x;
    const int lane = tid & 31, w = tid >> 5;
    const int m0 = blockIdx.x * BM;
    const int jb = blockIdx.y * BJ;
    const int t = mode ? (int)blockIdx.z : t_;

    const __nv_bfloat16 *Ah, *Al, *Wh, *Wl;
    if (mode) {
        Ah = g_x1_hi + (size_t)t * MTOT * KH;
        Al = g_x1_lo + (size_t)t * MTOT * KH;
        Wh = g_wx_hi; Wl = g_wx_lo;
    } else {
        Ah = g_zh_hi[par]; Al = g_zh_lo[par];
        Wh = g_wh_hi[layer]; Wl = g_wh_lo[layer];
    }

    // ---- per-thread load coords: A rows lr, lr+64 ; B rows lr+{0,64,128} ----
    const int lr = tid >> 2;        // 0..63
    const int lc = tid & 3;         // 16B chunk within 64B k-row
    const char* gA0h = (const char*)(Ah + (size_t)(m0 + lr) * KH) + lc * 16;
    const char* gA0l = (const char*)(Al + (size_t)(m0 + lr) * KH) + lc * 16;
    const char* gBh[3]; const char* gBl[3];
    uint32_t sBoff[3];
#pragma unroll
    for (int i = 0; i < 3; ++i) {
        int v = lr + i * 64;                        // n_local in [0,192)
        int wrow = (v >> 5) * 256 + jb + (v & 31);  // global weight row
        gBh[i] = (const char*)(Wh + (size_t)wrow * KH) + lc * 16;
        gBl[i] = (const char*)(Wl + (size_t)wrow * KH) + lc * 16;
        sBoff[i] = v * 80 + lc * 16;
    }
    const uint32_t sAoff = lr * 80 + lc * 16;

    float acc[2][NG][2][4];
#pragma unroll
    for (int mi = 0; mi < 2; ++mi)
#pragma unroll
        for (int g = 0; g < NG; ++g)
#pragma unroll
            for (int ni = 0; ni < 2; ++ni)
#pragma unroll
                for (int q = 0; q < 4; ++q) acc[mi][g][ni][q] = 0.0f;

    auto issue = [&](int c, int buf) {
        const uint32_t sb = sbase + buf * STAGE;
        const size_t go = (size_t)c * 64;           // 32 bf16 = 64B per chunk
        cp16(sb + S_AH + sAoff, gA0h + go);
        cp16(sb + S_AH + sAoff + 64 * 80, gA0h + 64 * KH * 2 + go);
        cp16(sb + S_AL + sAoff, gA0l + go);
        cp16(sb + S_AL + sAoff + 64 * 80, gA0l + 64 * KH * 2 + go);
#pragma unroll
        for (int i = 0; i < 3; ++i) {
            cp16(sb + S_BH + sBoff[i], gBh[i] + go);
            cp16(sb + S_BL + sBoff[i], gBl[i] + go);
        }
        CP_COMMIT();
    };

    const int mw = w >> 1;          // 0..3  (32 M-rows each)
    const int jw = w & 1;           // 0..1  (16 j each)
    const int fr = lane >> 2, fc = lane & 3;

    auto compute = [&](int buf) {
        const char* S = sm + buf * STAGE;
#pragma unroll
        for (int h = 0; h < 2; ++h) {
            uint32_t ah[2][4], al[2][4];
#pragma unroll
            for (int mi = 0; mi < 2; ++mi) {
                const char* pa = S + S_AH + (mw * 32 + mi * 16 + fr) * 80 + h * 32 + fc * 4;
                ah[mi][0] = *(const uint32_t*)pa;
                ah[mi][1] = *(const uint32_t*)(pa + 640);
                ah[mi][2] = *(const uint32_t*)(pa + 16);
                ah[mi][3] = *(const uint32_t*)(pa + 656);
                const char* pl = S + S_AL + (mw * 32 + mi * 16 + fr) * 80 + h * 32 + fc * 4;
                al[mi][0] = *(const uint32_t*)pl;
                al[mi][1] = *(const uint32_t*)(pl + 640);
                al[mi][2] = *(const uint32_t*)(pl + 16);
                al[mi][3] = *(const uint32_t*)(pl + 656);
            }
#pragma unroll
            for (int g = 0; g < NG; ++g) {
#pragma unroll
                for (int ni = 0; ni < 2; ++ni) {
                    const uint32_t roff = (g * 32 + jw * 16 + ni * 8 + fr) * 80 + h * 32 + fc * 4;
                    const char* pb = S + S_BH + roff;
                    uint32_t bh0 = *(const uint32_t*)pb;
                    uint32_t bh1 = *(const uint32_t*)(pb + 16);
                    const char* pbl = S + S_BL + roff;
                    uint32_t bl0 = *(const uint32_t*)pbl;
                    uint32_t bl1 = *(const uint32_t*)(pbl + 16);
#pragma unroll
                    for (int mi = 0; mi < 2; ++mi) {
                        MMA(acc[mi][g][ni], ah[mi], bh0, bh1);
                        MMA(acc[mi][g][ni], ah[mi], bl0, bl1);
                        MMA(acc[mi][g][ni], al[mi], bh0, bh1);
                    }
                }
            }
        }
    };

    // ---- pipelined K loop: 16 chunks of 32 ----
    issue(0, 0);
#pragma unroll 1
    for (int c = 0; c < 16; ++c) {
        if (c < 15) { issue(c + 1, (c + 1) & 1); CP_WAIT1(); }
        else        { CP_WAIT0(); }
        __syncthreads();
        compute(c & 1);
        __syncthreads();
    }

    // ---- epilogue ----
    if (mode) {
        // write x-gate contribution
#pragma unroll
        for (int mi = 0; mi < 2; ++mi)
#pragma unroll
            for (int rr = 0; rr < 2; ++rr) {
                int Ml = mw * 32 + mi * 16 + rr * 8 + fr;
                float* row = g_gx + ((size_t)t * MTOT + m0 + Ml) * NTOT;
#pragma unroll
                for (int ni = 0; ni < 2; ++ni) {
                    int j0 = jb + jw * 16 + ni * 8 + fc * 2;
#pragma unroll
                    for (int g = 0; g < NG; ++g) {
                        float2 v = make_float2(acc[mi][g][ni][rr * 2], acc[mi][g][ni][rr * 2 + 1]);
                        *(float2*)(row + g * 256 + j0) = v;
                    }
                }
            }
        return;
    }

    // SEQ: fused pointwise
    const int wb = par ^ 1;
#pragma unroll
    for (int mi = 0; mi < 2; ++mi)
#pragma unroll
        for (int rr = 0; rr < 2; ++rr) {
            const int Ml = mw * 32 + mi * 16 + rr * 8 + fr;
            const int M = m0 + Ml;
            const int r = M >> 6, b = M & 63;
            const bool addb = (r <= t) && (t < RR);
#pragma unroll
            for (int ni = 0; ni < 2; ++ni) {
                const int j0 = jb + jw * 16 + ni * 8 + fc * 2;
                const float* gxp = g_gx + ((size_t)t * MTOT + M) * NTOT + j0;
                float v[NG][2];
#pragma unroll
                for (int g = 0; g < NG; ++g) {
                    float2 gxv = *(const float2*)(gxp + g * 256);
                    v[g][0] = acc[mi][g][ni][rr * 2] + gxv.x;
                    v[g][1] = acc[mi][g][ni][rr * 2 + 1] + gxv.y;
                    if (addb) { v[g][0] += Bias[g * 256 + j0]; v[g][1] += Bias[g * 256 + j0 + 1]; }
                }
                const size_t hidx = (size_t)M * HH + j0;
                float2 hro = *(const float2*)&g_hrow[par][hidx];
                float2 hco = *(const float2*)&g_hcol[par][hidx];
                float hr[2], hc[2];
#pragma unroll
                for (int jj = 0; jj < 2; ++jj) {
                    float ur = sigmoidf_(v[0][jj]);
                    float orr = sigmoidf_(v[1][jj]);
                    float uc = sigmoidf_(v[2][jj]);
                    float oc = sigmoidf_(v[3][jj]);
                    float ir = tanhf(v[4][jj]);
                    float ic = tanhf(v[5][jj]);
                    float ho = jj ? hro.y : hro.x;
                    float co = jj ? hco.y : hco.x;
                    hr[jj] = tanhf((1.0f - ur) * ho + ur * ir) * orr;
                    hc[jj] = tanhf((1.0f - uc) * co + uc * ic) * oc;
                }
                *(float2*)&g_hrow[wb][hidx] = make_float2(hr[0], hr[1]);
                const int Mr = (((r + 1) & 31) << 6) | b;        // roll(h_col,+1,axis=0)
                *(float2*)&g_hcol[wb][(size_t)Mr * HH + j0] = make_float2(hc[0], hc[1]);

                // next-step Z (bf16 hi/lo)
                __nv_bfloat16 h0 = __float2bfloat16(hr[0]), h1 = __float2bfloat16(hr[1]);
                float l0 = hr[0] - __bfloat162float(h0), l1 = hr[1] - __bfloat162float(h1);
                *(uint32_t*)&g_zh_hi[wb][(size_t)M * KH + j0] = bfpack(hr[0], hr[1]);
                *(uint32_t*)&g_zh_lo[wb][(size_t)M * KH + j0] = bfpack(l0, l1);
                __nv_bfloat16 c0 = __float2bfloat16(hc[0]), c1 = __float2bfloat16(hc[1]);
                float m0c = hc[0] - __bfloat162float(c0), m1c = hc[1] - __bfloat162float(c1);
                *(uint32_t*)&g_zh_hi[wb][(size_t)Mr * KH + 256 + j0] = bfpack(hc[0], hc[1]);
                *(uint32_t*)&g_zh_lo[wb][(size_t)Mr * KH + 256 + j0] = bfpack(m0c, m1c);

                if (layer == 0) {
                    // layer-1 x input (un-rolled concat), bf16 hi/lo
                    const size_t xb = ((size_t)t * MTOT + M) * KH;
                    *(uint32_t*)&g_x1_hi[xb + j0] = bfpack(hr[0], hr[1]);
                    *(uint32_t*)&g_x1_lo[xb + j0] = bfpack(l0, l1);
                    *(uint32_t*)&g_x1_hi[xb + 256 + j0] = bfpack(hc[0], hc[1]);
                    *(uint32_t*)&g_x1_lo[xb + 256 + j0] = bfpack(m0c, m1c);
                } else {
                    const size_t ob = ((size_t)M * LLEN + t) * 512;
                    *(float2*)&dout[ob + j0] = make_float2(hr[0], hr[1]);
                    *(float2*)&dout[ob + 256 + j0] = make_float2(hc[0], hc[1]);
                }
                if (t >= RR - 1) {
                    const int k = t - (RR - 1);
                    if (r == k)
                        *(float2*)&dout[OFF1 + (((size_t)b * 2 + layer) * RR + k) * HH + j0] =
                            make_float2(hr[0], hr[1]);
                    if (r == RR - 1)
                        *(float2*)&dout[OFF2 + (((size_t)b * 2 + layer) * RR + k) * HH + j0] =
                            make_float2(hc[0], hc[1]);
                }
            }
        }
}

// ---------------- host ----------------
extern "C" void kernel_launch(void* const* d_in, const int* in_sizes, int n_in,
                              void* d_out, int out_size) {
    (void)in_sizes; (void)n_in; (void)out_size;
    const float* inp  = (const float*)d_in[0];
    const float* Wf   = (const float*)d_in[1];
    const float* Wo   = (const float*)d_in[2];
    const float* Bias = (const float*)d_in[3];
    float* out = (float*)d_out;

    static bool attr_done = false;
    if (!attr_done) {
        cudaFuncSetAttribute(gemm_k, cudaFuncAttributeMaxDynamicSharedMemorySize, SMEMT);
        attr_done = true;
    }

    prep_w<<<512, 256>>>(Wf, Wo);
    gx0_kernel<<<LLEN * MTOT, 256>>>(inp, Wf);

    dim3 sgrid(MTOT / BM, HH / BJ);          // 16 x 8 = 128 CTAs
    // layer 0
    init_h<<<(MTOT * KH + 255) / 256, 256>>>();
    for (int t = 0; t < LLEN; ++t)
        gemm_k<<<sgrid, 256, SMEMT>>>(0, 0, t, t & 1, Bias, out);
    // batched layer-1 x-contribution
    {
        dim3 bgrid(MTOT / BM, HH / BJ, LLEN);
        gemm_k<<<bgrid, 256, SMEMT>>>(1, 1, 0, 0, Bias, out);
    }
    // layer 1
    init_h<<<(MTOT * KH + 255) / 256, 256>>>();
    for (int t = 0; t < LLEN; ++t)
        gemm_k<<<sgrid, 256, SMEMT>>>(0, 1, t, t & 1, Bias + NTOT, out);
}

// round 4
// speedup vs baseline: 2.3756x; 1.0373x over previous
#include <cuda_runtime.h>
#include <cuda_bf16.h>
#include <math.h>
#include <stdint.h>

// ---------------- problem constants ----------------
#define RR    32
#define LLEN  63
#define HH    256
#define MTOT  2048
#define NG    6
#define KH    512            // sequential K (h_row 256 + h_col 256)
#define NTOT  1536
#define OFF1  66060288ull
#define OFF2  67108864ull

// ---------------- device scratch ----------------
__device__ float g_hrow[2][MTOT * HH];
__device__ float g_hcol[2][MTOT * HH];
__device__ __nv_bfloat16 g_zh_hi[2][MTOT * KH];
__device__ __nv_bfloat16 g_zh_lo[2][MTOT * KH];
__device__ __nv_bfloat16 g_x1_hi[(size_t)LLEN * MTOT * KH];
__device__ __nv_bfloat16 g_x1_lo[(size_t)LLEN * MTOT * KH];
__device__ __nv_bfloat16 g_wh_hi[2][NTOT * KH];
__device__ __nv_bfloat16 g_wh_lo[2][NTOT * KH];
__device__ __nv_bfloat16 g_wx_hi[NTOT * KH];
__device__ __nv_bfloat16 g_wx_lo[NTOT * KH];
__device__ float g_gx[(size_t)LLEN * MTOT * NTOT];   // per-step x-contribution of gates

// ---------------- helpers ----------------
__device__ __forceinline__ uint32_t smem_u32(const void* p) {
    uint32_t a;
    asm("{ .reg .u64 t; cvta.to.shared.u64 t, %1; cvt.u32.u64 %0, t; }" : "=r"(a) : "l"(p));
    return a;
}
__device__ __forceinline__ void cp16(uint32_t s, const void* g) {
    asm volatile("cp.async.cg.shared.global [%0], [%1], 16;" :: "r"(s), "l"(g));
}
#define CP_COMMIT() asm volatile("cp.async.commit_group;")
#define CP_WAIT1()  asm volatile("cp.async.wait_group 1;")
#define CP_WAIT0()  asm volatile("cp.async.wait_group 0;")

#define MMA(accp, a, b0, b1) \
    asm volatile("mma.sync.aligned.m16n8k16.row.col.f32.bf16.bf16.f32 " \
        "{%0,%1,%2,%3}, {%4,%5,%6,%7}, {%8,%9}, {%0,%1,%2,%3};" \
        : "+f"((accp)[0]), "+f"((accp)[1]), "+f"((accp)[2]), "+f"((accp)[3]) \
        : "r"((a)[0]), "r"((a)[1]), "r"((a)[2]), "r"((a)[3]), "r"(b0), "r"(b1))

#define LDSM4(r, addr) \
    asm volatile("ldmatrix.sync.aligned.m8n8.x4.shared.b16 {%0,%1,%2,%3}, [%4];" \
        : "=r"((r)[0]), "=r"((r)[1]), "=r"((r)[2]), "=r"((r)[3]) : "r"(addr))

__device__ __forceinline__ float sigmoidf_(float x) { return 1.0f / (1.0f + __expf(-x)); }
__device__ __forceinline__ uint32_t bfpack(float x, float y) {
    __nv_bfloat162 p = __floats2bfloat162_rn(x, y);
    return *reinterpret_cast<uint32_t*>(&p);
}

// ---------------- smem layout (per stage) ----------------
// rows padded to 80B (32 bf16 data + 16B pad) -> conflict-free cp.async + ldmatrix
#define BM 128
#define BJ 16                  // j per CTA (x6 gates = 96 N-rows)
#define S_AH 0                 // A hi: 128 rows x 80B = 10240
#define S_AL 10240
#define S_BH 20480             // B hi: 96 rows x 80B = 7680
#define S_BL 28160
#define STAGE 35840
#define SMEMT (2 * STAGE)      // 71680 -> 2 CTAs/SM

// ---------------- prep kernels ----------------
__global__ void prep_w(const float* __restrict__ Wf, const float* __restrict__ Wo) {
    const int N = NTOT * KH;
    for (int i = blockIdx.x * blockDim.x + threadIdx.x; i < 3 * N; i += gridDim.x * blockDim.x) {
        int rgn = i / N, j = i % N;
        int n = j / KH, k = j % KH;
        float v;
        __nv_bfloat16 *dh, *dl;
        if (rgn == 0)      { v = Wf[(size_t)n * 520 + k];        dh = g_wh_hi[0]; dl = g_wh_lo[0]; }
        else if (rgn == 1) { v = Wo[(size_t)n * 1024 + k];       dh = g_wh_hi[1]; dl = g_wh_lo[1]; }
        else               { v = Wo[(size_t)n * 1024 + 512 + k]; dh = g_wx_hi;    dl = g_wx_lo;    }
        __nv_bfloat16 hi = __float2bfloat16(v);
        dh[j] = hi;
        dl[j] = __float2bfloat16(v - __bfloat162float(hi));
    }
}

// layer-0 x-contribution: g_gx[t,M,n] = sum_{k<8} x0(t,M,k) * Wf[n][512+k]  (exact fp32)
__global__ void gx0_kernel(const float* __restrict__ inp, const float* __restrict__ Wf) {
    const int blk = blockIdx.x;                 // t*2048 + M
    const int t = blk >> 11, M = blk & (MTOT - 1);
    const int r = M >> 6, b = M & 63, c = t - r;
    const bool valid = (c >= 0 && c < 32);
    float x[8];
    if (valid) {
#pragma unroll
        for (int k = 0; k < 8; ++k)
            x[k] = inp[(((size_t)b * RR + r) * 32 + c) * 8 + k];
    }
    float* dst = g_gx + (size_t)blk * NTOT;
    for (int n = threadIdx.x; n < NTOT; n += blockDim.x) {
        float s = 0.0f;
        if (valid) {
            const float* w = Wf + (size_t)n * 520 + 512;
#pragma unroll
            for (int k = 0; k < 8; ++k) s += x[k] * w[k];
        }
        dst[n] = s;
    }
}

__global__ void init_h() {
    int i = blockIdx.x * blockDim.x + threadIdx.x;
    if (i < MTOT * KH) {
        g_zh_hi[0][i] = __float2bfloat16(0.0f);
        g_zh_lo[0][i] = __float2bfloat16(0.0f);
        if (i < MTOT * HH) { g_hrow[0][i] = 0.0f; g_hcol[0][i] = 0.0f; }
    }
}

// ---------------- fused GEMM (+ pointwise epilogue in SEQ mode) ----------------
// mode 0 (SEQ):   D = zh[par] @ Wh[layer]^T + g_gx[t] (+bias) -> pointwise update
// mode 1 (BATCH): g_gx[t] = X1[t] @ Wx^T   (t = blockIdx.z)
__global__ __launch_bounds__(256, 2) void gemm_k(
    int mode, int layer, int t_, int par,
    const float* __restrict__ Bias, float* __restrict__ dout)
{
    extern __shared__ char sm[];
    const uint32_t sbase = smem_u32(sm);
    const int tid = threadIdx.x;
    const int lane = tid & 31, w = tid >> 5;
    const int m0 = blockIdx.x * BM;
    const int jb = blockIdx.y * BJ;
    const int t = mode ? (int)blockIdx.z : t_;

    const __nv_bfloat16 *Ah, *Al, *Wh, *Wl;
    if (mode) {
        Ah = g_x1_hi + (size_t)t * MTOT * KH;
        Al = g_x1_lo + (size_t)t * MTOT * KH;
        Wh = g_wx_hi; Wl = g_wx_lo;
    } else {
        Ah = g_zh_hi[par]; Al = g_zh_lo[par];
        Wh = g_wh_hi[layer]; Wl = g_wh_lo[layer];
    }

    // ---- cp.async coords ----
    const int lr = tid >> 2;        // 0..63
    const int lc = tid & 3;         // 16B chunk in 64B k-slab
    const char* gA0h = (const char*)(Ah + (size_t)(m0 + lr) * KH) + lc * 16;
    const char* gA0l = (const char*)(Al + (size_t)(m0 + lr) * KH) + lc * 16;
    const uint32_t sAoff = lr * 80 + lc * 16;
    // B: 96 hi rows + 96 lo rows = 192 row-streams, 3 per thread
    const char* gB[3];
    uint32_t sBoff[3];
#pragma unroll
    for (int i = 0; i < 3; ++i) {
        int v = lr + i * 64;                 // 0..191
        int v96 = (v < 96) ? v : v - 96;
        int wrow = (v96 >> 4) * 256 + jb + (v96 & 15);
        const __nv_bfloat16* base = (v < 96) ? Wh : Wl;
        gB[i] = (const char*)(base + (size_t)wrow * KH) + lc * 16;
        sBoff[i] = ((v < 96) ? S_BH : S_BL) + v96 * 80 + lc * 16;
    }

    float acc[NG][2][4];
#pragma unroll
    for (int g = 0; g < NG; ++g)
#pragma unroll
        for (int nt = 0; nt < 2; ++nt)
#pragma unroll
            for (int q = 0; q < 4; ++q) acc[g][nt][q] = 0.0f;

    auto issue = [&](int c, int buf) {
        const uint32_t sb = sbase + buf * STAGE;
        const size_t go = (size_t)c * 64;
        cp16(sb + S_AH + sAoff, gA0h + go);
        cp16(sb + S_AH + sAoff + 64 * 80, gA0h + (size_t)64 * KH * 2 + go);
        cp16(sb + S_AL + sAoff, gA0l + go);
        cp16(sb + S_AL + sAoff + 64 * 80, gA0l + (size_t)64 * KH * 2 + go);
#pragma unroll
        for (int i = 0; i < 3; ++i) cp16(sb + sBoff[i], gB[i] + go);
        CP_COMMIT();
    };

    // ---- ldmatrix lane coords ----
    const int aRow = (lane & 7) + ((lane >> 3) & 1) * 8;   // m within warp tile
    const int aKoff = ((lane >> 4) & 1) * 16;
    const int bRow = (lane & 7) + (((lane >> 4) & 1) ? 8 : 0);
    const int bKoff = ((lane >> 3) & 1) * 16;
    const uint32_t aBase = (w * 16 + aRow) * 80 + aKoff;
    const uint32_t bBase = bRow * 80 + bKoff;

    auto compute = [&](int buf) {
        const uint32_t S = sbase + buf * STAGE;
#pragma unroll
        for (int h = 0; h < 2; ++h) {
            uint32_t ah[4], al[4];
            uint32_t aAddr = S + S_AH + aBase + h * 32;
            LDSM4(ah, aAddr);
            LDSM4(al, aAddr + (S_AL - S_AH));
#pragma unroll
            for (int g = 0; g < NG; ++g) {
                uint32_t bh[4], bl[4];
                uint32_t bAddr = S + S_BH + g * 16 * 80 + bBase + h * 32;
                LDSM4(bh, bAddr);
                LDSM4(bl, bAddr + (S_BL - S_BH));
                MMA(acc[g][0], ah, bh[0], bh[1]);
                MMA(acc[g][0], ah, bl[0], bl[1]);
                MMA(acc[g][0], al, bh[0], bh[1]);
                MMA(acc[g][1], ah, bh[2], bh[3]);
                MMA(acc[g][1], ah, bl[2], bl[3]);
                MMA(acc[g][1], al, bh[2], bh[3]);
            }
        }
    };

    // ---- pipelined K loop: 16 chunks of 32 ----
    issue(0, 0);
#pragma unroll 1
    for (int c = 0; c < 16; ++c) {
        if (c < 15) { issue(c + 1, (c + 1) & 1); CP_WAIT1(); }
        else        { CP_WAIT0(); }
        __syncthreads();
        compute(c & 1);
        __syncthreads();
    }

    const int fr = lane >> 2, fc = lane & 3;

    // ---- epilogue ----
    if (mode) {
#pragma unroll
        for (int rr = 0; rr < 2; ++rr) {
            const int Ml = w * 16 + rr * 8 + fr;
            float* row = g_gx + ((size_t)t * MTOT + m0 + Ml) * NTOT;
#pragma unroll
            for (int nt = 0; nt < 2; ++nt) {
                const int j0 = jb + nt * 8 + fc * 2;
#pragma unroll
                for (int g = 0; g < NG; ++g)
                    *(float2*)(row + g * 256 + j0) =
                        make_float2(acc[g][nt][rr * 2], acc[g][nt][rr * 2 + 1]);
            }
        }
        return;
    }

    // SEQ: fused pointwise
    const int wb = par ^ 1;
#pragma unroll
    for (int rr = 0; rr < 2; ++rr) {
        const int M = m0 + w * 16 + rr * 8 + fr;
        const int r = M >> 6, b = M & 63;
        const bool addb = (r <= t) && (t < RR);
#pragma unroll
        for (int nt = 0; nt < 2; ++nt) {
            const int j0 = jb + nt * 8 + fc * 2;
            const float* gxp = g_gx + ((size_t)t * MTOT + M) * NTOT + j0;
            float v[NG][2];
#pragma unroll
            for (int g = 0; g < NG; ++g) {
                float2 gxv = *(const float2*)(gxp + g * 256);
                v[g][0] = acc[g][nt][rr * 2] + gxv.x;
                v[g][1] = acc[g][nt][rr * 2 + 1] + gxv.y;
                if (addb) { v[g][0] += Bias[g * 256 + j0]; v[g][1] += Bias[g * 256 + j0 + 1]; }
            }
            const size_t hidx = (size_t)M * HH + j0;
            float2 hro = *(const float2*)&g_hrow[par][hidx];
            float2 hco = *(const float2*)&g_hcol[par][hidx];
            float hr[2], hc[2];
#pragma unroll
            for (int jj = 0; jj < 2; ++jj) {
                float ur = sigmoidf_(v[0][jj]);
                float orr = sigmoidf_(v[1][jj]);
                float uc = sigmoidf_(v[2][jj]);
                float oc = sigmoidf_(v[3][jj]);
                float ir = tanhf(v[4][jj]);
                float ic = tanhf(v[5][jj]);
                float ho = jj ? hro.y : hro.x;
                float co = jj ? hco.y : hco.x;
                hr[jj] = tanhf((1.0f - ur) * ho + ur * ir) * orr;
                hc[jj] = tanhf((1.0f - uc) * co + uc * ic) * oc;
            }
            *(float2*)&g_hrow[wb][hidx] = make_float2(hr[0], hr[1]);
            const int Mr = (((r + 1) & 31) << 6) | b;        // roll(h_col,+1,axis=0)
            *(float2*)&g_hcol[wb][(size_t)Mr * HH + j0] = make_float2(hc[0], hc[1]);

            // next-step Z (bf16 hi/lo)
            __nv_bfloat16 h0 = __float2bfloat16(hr[0]), h1 = __float2bfloat16(hr[1]);
            float l0 = hr[0] - __bfloat162float(h0), l1 = hr[1] - __bfloat162float(h1);
            *(uint32_t*)&g_zh_hi[wb][(size_t)M * KH + j0] = bfpack(hr[0], hr[1]);
            *(uint32_t*)&g_zh_lo[wb][(size_t)M * KH + j0] = bfpack(l0, l1);
            __nv_bfloat16 c0 = __float2bfloat16(hc[0]), c1 = __float2bfloat16(hc[1]);
            float m0c = hc[0] - __bfloat162float(c0), m1c = hc[1] - __bfloat162float(c1);
            *(uint32_t*)&g_zh_hi[wb][(size_t)Mr * KH + 256 + j0] = bfpack(hc[0], hc[1]);
            *(uint32_t*)&g_zh_lo[wb][(size_t)Mr * KH + 256 + j0] = bfpack(m0c, m1c);

            if (layer == 0) {
                const size_t xb = ((size_t)t * MTOT + M) * KH;
                *(uint32_t*)&g_x1_hi[xb + j0] = bfpack(hr[0], hr[1]);
                *(uint32_t*)&g_x1_lo[xb + j0] = bfpack(l0, l1);
                *(uint32_t*)&g_x1_hi[xb + 256 + j0] = bfpack(hc[0], hc[1]);
                *(uint32_t*)&g_x1_lo[xb + 256 + j0] = bfpack(m0c, m1c);
            } else {
                const size_t ob = ((size_t)M * LLEN + t) * 512;
                *(float2*)&dout[ob + j0] = make_float2(hr[0], hr[1]);
                *(float2*)&dout[ob + 256 + j0] = make_float2(hc[0], hc[1]);
            }
            if (t >= RR - 1) {
                const int k = t - (RR - 1);
                if (r == k)
                    *(float2*)&dout[OFF1 + (((size_t)b * 2 + layer) * RR + k) * HH + j0] =
                        make_float2(hr[0], hr[1]);
                if (r == RR - 1)
                    *(float2*)&dout[OFF2 + (((size_t)b * 2 + layer) * RR + k) * HH + j0] =
                        make_float2(hc[0], hc[1]);
            }
        }
    }
}

// ---------------- host ----------------
extern "C" void kernel_launch(void* const* d_in, const int* in_sizes, int n_in,
                              void* d_out, int out_size) {
    (void)in_sizes; (void)n_in; (void)out_size;
    const float* inp  = (const float*)d_in[0];
    const float* Wf   = (const float*)d_in[1];
    const float* Wo   = (const float*)d_in[2];
    const float* Bias = (const float*)d_in[3];
    float* out = (float*)d_out;

    cudaFuncSetAttribute(gemm_k, cudaFuncAttributeMaxDynamicSharedMemorySize, SMEMT);

    prep_w<<<512, 256>>>(Wf, Wo);
    gx0_kernel<<<LLEN * MTOT, 256>>>(inp, Wf);

    dim3 sgrid(MTOT / BM, HH / BJ);          // 16 x 16 = 256 CTAs
    // layer 0
    init_h<<<(MTOT * KH + 255) / 256, 256>>>();
    for (int t = 0; t < LLEN; ++t)
        gemm_k<<<sgrid, 256, SMEMT>>>(0, 0, t, t & 1, Bias, out);
    // batched layer-1 x-contribution
    {
        dim3 bgrid(MTOT / BM, HH / BJ, LLEN);
        gemm_k<<<bgrid, 256, SMEMT>>>(1, 1, 0, 0, Bias, out);
    }
    // layer 1
    init_h<<<(MTOT * KH + 255) / 256, 256>>>();
    for (int t = 0; t < LLEN; ++t)
        gemm_k<<<sgrid, 256, SMEMT>>>(0, 1, t, t & 1, Bias + NTOT, out);
}

// round 5
// speedup vs baseline: 2.4434x; 1.0286x over previous
#include <cuda_runtime.h>
#include <cuda_bf16.h>
#include <math.h>
#include <stdint.h>

// ---------------- problem constants ----------------
#define RR    32
#define LLEN  63
#define HH    256
#define MTOT  2048
#define NG    6
#define KH    512            // sequential K (h_row 256 + h_col 256)
#define NTOT  1536
#define OFF1  66060288ull
#define OFF2  67108864ull

// ---------------- device scratch ----------------
__device__ float g_hrow[2][MTOT * HH];
__device__ float g_hcol[2][MTOT * HH];
__device__ __nv_bfloat16 g_zh_hi[2][MTOT * KH];
__device__ __nv_bfloat16 g_zh_lo[2][MTOT * KH];
__device__ __nv_bfloat16 g_x1_hi[(size_t)LLEN * MTOT * KH];
__device__ __nv_bfloat16 g_x1_lo[(size_t)LLEN * MTOT * KH];
__device__ __nv_bfloat16 g_wh_hi[2][NTOT * KH];
__device__ __nv_bfloat16 g_wh_lo[2][NTOT * KH];
__device__ __nv_bfloat16 g_wx_hi[NTOT * KH];
__device__ __nv_bfloat16 g_wx_lo[NTOT * KH];
__device__ float g_gx[(size_t)LLEN * MTOT * NTOT];   // per-step x-contribution of gates

// ---------------- helpers ----------------
__device__ __forceinline__ uint32_t smem_u32(const void* p) {
    uint32_t a;
    asm("{ .reg .u64 t; cvta.to.shared.u64 t, %1; cvt.u32.u64 %0, t; }" : "=r"(a) : "l"(p));
    return a;
}
__device__ __forceinline__ void cp16(uint32_t s, const void* g) {
    asm volatile("cp.async.cg.shared.global [%0], [%1], 16;" :: "r"(s), "l"(g));
}
#define CP_COMMIT() asm volatile("cp.async.commit_group;")
#define CP_WAIT1()  asm volatile("cp.async.wait_group 1;")
#define CP_WAIT0()  asm volatile("cp.async.wait_group 0;")

#define MMA(accp, a, b0, b1) \
    asm volatile("mma.sync.aligned.m16n8k16.row.col.f32.bf16.bf16.f32 " \
        "{%0,%1,%2,%3}, {%4,%5,%6,%7}, {%8,%9}, {%0,%1,%2,%3};" \
        : "+f"((accp)[0]), "+f"((accp)[1]), "+f"((accp)[2]), "+f"((accp)[3]) \
        : "r"((a)[0]), "r"((a)[1]), "r"((a)[2]), "r"((a)[3]), "r"(b0), "r"(b1))

#define LDSM4(r, addr) \
    asm volatile("ldmatrix.sync.aligned.m8n8.x4.shared.b16 {%0,%1,%2,%3}, [%4];" \
        : "=r"((r)[0]), "=r"((r)[1]), "=r"((r)[2]), "=r"((r)[3]) : "r"(addr))

__device__ __forceinline__ float sigmoidf_(float x) { return 1.0f / (1.0f + __expf(-x)); }
__device__ __forceinline__ uint32_t bfpack(float x, float y) {
    __nv_bfloat162 p = __floats2bfloat162_rn(x, y);
    return *reinterpret_cast<uint32_t*>(&p);
}

// ---------------- smem layout (per stage) ----------------
// rows padded to 80B (32 bf16 data + 16B pad) -> conflict-free cp.async + ldmatrix
#define BM 128
#define BJ 16                  // j per CTA (x6 gates = 96 N-rows)
#define S_AH 0                 // A hi: 128 rows x 80B = 10240
#define S_AL 10240
#define S_BH 20480             // B hi: 96 rows x 80B = 7680
#define S_BL 28160
#define STAGE 35840
#define NSTAGE 3
#define SMEMT (NSTAGE * STAGE)   // 107520 -> 2 CTAs/SM (215KB of 228KB)

// ---------------- prep kernels ----------------
__global__ void prep_w(const float* __restrict__ Wf, const float* __restrict__ Wo) {
    const int N = NTOT * KH;
    for (int i = blockIdx.x * blockDim.x + threadIdx.x; i < 3 * N; i += gridDim.x * blockDim.x) {
        int rgn = i / N, j = i % N;
        int n = j / KH, k = j % KH;
        float v;
        __nv_bfloat16 *dh, *dl;
        if (rgn == 0)      { v = Wf[(size_t)n * 520 + k];        dh = g_wh_hi[0]; dl = g_wh_lo[0]; }
        else if (rgn == 1) { v = Wo[(size_t)n * 1024 + k];       dh = g_wh_hi[1]; dl = g_wh_lo[1]; }
        else               { v = Wo[(size_t)n * 1024 + 512 + k]; dh = g_wx_hi;    dl = g_wx_lo;    }
        __nv_bfloat16 hi = __float2bfloat16(v);
        dh[j] = hi;
        dl[j] = __float2bfloat16(v - __bfloat162float(hi));
    }
}

// layer-0 x-contribution: g_gx[t,M,n] = sum_{k<8} x0(t,M,k) * Wf[n][512+k]  (exact fp32)
__global__ void gx0_kernel(const float* __restrict__ inp, const float* __restrict__ Wf) {
    const int blk = blockIdx.x;                 // t*2048 + M
    const int t = blk >> 11, M = blk & (MTOT - 1);
    const int r = M >> 6, b = M & 63, c = t - r;
    const bool valid = (c >= 0 && c < 32);
    float x[8];
    if (valid) {
#pragma unroll
        for (int k = 0; k < 8; ++k)
            x[k] = inp[(((size_t)b * RR + r) * 32 + c) * 8 + k];
    }
    float* dst = g_gx + (size_t)blk * NTOT;
    for (int n = threadIdx.x; n < NTOT; n += blockDim.x) {
        float s = 0.0f;
        if (valid) {
            const float* w = Wf + (size_t)n * 520 + 512;
#pragma unroll
            for (int k = 0; k < 8; ++k) s += x[k] * w[k];
        }
        dst[n] = s;
    }
}

__global__ void init_h() {
    int i = blockIdx.x * blockDim.x + threadIdx.x;
    if (i < MTOT * KH) {
        g_zh_hi[0][i] = __float2bfloat16(0.0f);
        g_zh_lo[0][i] = __float2bfloat16(0.0f);
        if (i < MTOT * HH) { g_hrow[0][i] = 0.0f; g_hcol[0][i] = 0.0f; }
    }
}

// ---------------- fused GEMM (+ pointwise epilogue in SEQ mode) ----------------
// mode 0 (SEQ):   D = zh[par] @ Wh[layer]^T + g_gx[t] (+bias) -> pointwise update
// mode 1 (BATCH): g_gx[t] = X1[t] @ Wx^T   (t = blockIdx.z)
__global__ __launch_bounds__(256, 2) void gemm_k(
    int mode, int layer, int t_, int par,
    const float* __restrict__ Bias, float* __restrict__ dout)
{
    extern __shared__ char sm[];
    const uint32_t sbase = smem_u32(sm);
    const int tid = threadIdx.x;
    const int lane = tid & 31, w = tid >> 5;
    const int m0 = blockIdx.x * BM;
    const int jb = blockIdx.y * BJ;
    const int t = mode ? (int)blockIdx.z : t_;

    // triangle skip: rows r > t are identically zero; matching SEQ consumers
    // skip-read the same blocks, so batch CTAs with both r's > t do nothing.
    if (mode && (2 * (int)blockIdx.x > t)) return;

    const __nv_bfloat16 *Ah, *Al, *Wh, *Wl;
    if (mode) {
        Ah = g_x1_hi + (size_t)t * MTOT * KH;
        Al = g_x1_lo + (size_t)t * MTOT * KH;
        Wh = g_wx_hi; Wl = g_wx_lo;
    } else {
        Ah = g_zh_hi[par]; Al = g_zh_lo[par];
        Wh = g_wh_hi[layer]; Wl = g_wh_lo[layer];
    }

    // ---- cp.async coords ----
    const int lr = tid >> 2;        // 0..63
    const int lc = tid & 3;         // 16B chunk in 64B k-slab
    const char* gA0h = (const char*)(Ah + (size_t)(m0 + lr) * KH) + lc * 16;
    const char* gA0l = (const char*)(Al + (size_t)(m0 + lr) * KH) + lc * 16;
    const uint32_t sAoff = lr * 80 + lc * 16;
    // B: 96 hi rows + 96 lo rows = 192 row-streams, 3 per thread
    const char* gB[3];
    uint32_t sBoff[3];
#pragma unroll
    for (int i = 0; i < 3; ++i) {
        int v = lr + i * 64;                 // 0..191
        int v96 = (v < 96) ? v : v - 96;
        int wrow = (v96 >> 4) * 256 + jb + (v96 & 15);
        const __nv_bfloat16* base = (v < 96) ? Wh : Wl;
        gB[i] = (const char*)(base + (size_t)wrow * KH) + lc * 16;
        sBoff[i] = ((v < 96) ? S_BH : S_BL) + v96 * 80 + lc * 16;
    }

    float acc[NG][2][4];
#pragma unroll
    for (int g = 0; g < NG; ++g)
#pragma unroll
        for (int nt = 0; nt < 2; ++nt)
#pragma unroll
            for (int q = 0; q < 4; ++q) acc[g][nt][q] = 0.0f;

    auto issue = [&](int c, int buf) {
        const uint32_t sb = sbase + buf * STAGE;
        const size_t go = (size_t)c * 64;
        cp16(sb + S_AH + sAoff, gA0h + go);
        cp16(sb + S_AH + sAoff + 64 * 80, gA0h + (size_t)64 * KH * 2 + go);
        cp16(sb + S_AL + sAoff, gA0l + go);
        cp16(sb + S_AL + sAoff + 64 * 80, gA0l + (size_t)64 * KH * 2 + go);
#pragma unroll
        for (int i = 0; i < 3; ++i) cp16(sb + sBoff[i], gB[i] + go);
        CP_COMMIT();
    };

    // ---- ldmatrix lane coords ----
    const int aRow = (lane & 7) + ((lane >> 3) & 1) * 8;   // m within warp tile
    const int aKoff = ((lane >> 4) & 1) * 16;
    const int bRow = (lane & 7) + (((lane >> 4) & 1) ? 8 : 0);
    const int bKoff = ((lane >> 3) & 1) * 16;
    const uint32_t aBase = (w * 16 + aRow) * 80 + aKoff;
    const uint32_t bBase = bRow * 80 + bKoff;

    auto compute = [&](int buf) {
        const uint32_t S = sbase + buf * STAGE;
#pragma unroll
        for (int h = 0; h < 2; ++h) {
            uint32_t ah[4], al[4];
            uint32_t aAddr = S + S_AH + aBase + h * 32;
            LDSM4(ah, aAddr);
            LDSM4(al, aAddr + (S_AL - S_AH));
#pragma unroll
            for (int g = 0; g < NG; ++g) {
                uint32_t bh[4], bl[4];
                uint32_t bAddr = S + S_BH + g * 16 * 80 + bBase + h * 32;
                LDSM4(bh, bAddr);
                LDSM4(bl, bAddr + (S_BL - S_BH));
                MMA(acc[g][0], ah, bh[0], bh[1]);
                MMA(acc[g][0], ah, bl[0], bl[1]);
                MMA(acc[g][0], al, bh[0], bh[1]);
                MMA(acc[g][1], ah, bh[2], bh[3]);
                MMA(acc[g][1], ah, bl[2], bl[3]);
                MMA(acc[g][1], al, bh[2], bh[3]);
            }
        }
    };

    // ---- 3-stage pipelined K loop: 16 chunks of 32, ONE syncthreads/chunk ----
    // iter c: wait stage c ready (<=1 group pending), sync (publishes stage c AND
    // retires stage c-1 across the CTA), then refill buffer (c+2)%3, then compute.
    issue(0, 0);
    issue(1, 1);
#pragma unroll 1
    for (int c = 0; c < 16; ++c) {
        if (c < 15) CP_WAIT1(); else CP_WAIT0();
        __syncthreads();
        if (c < 14) issue(c + 2, (c + 2) % NSTAGE);
        compute(c % NSTAGE);
    }

    const int fr = lane >> 2, fc = lane & 3;

    // ---- epilogue ----
    if (mode) {
#pragma unroll
        for (int rr = 0; rr < 2; ++rr) {
            const int Ml = w * 16 + rr * 8 + fr;
            float* row = g_gx + ((size_t)t * MTOT + m0 + Ml) * NTOT;
#pragma unroll
            for (int nt = 0; nt < 2; ++nt) {
                const int j0 = jb + nt * 8 + fc * 2;
#pragma unroll
                for (int g = 0; g < NG; ++g)
                    *(float2*)(row + g * 256 + j0) =
                        make_float2(acc[g][nt][rr * 2], acc[g][nt][rr * 2 + 1]);
            }
        }
        return;
    }

    // SEQ: fused pointwise
    const int wb = par ^ 1;
#pragma unroll
    for (int rr = 0; rr < 2; ++rr) {
        const int M = m0 + w * 16 + rr * 8 + fr;
        const int r = M >> 6, b = M & 63;
        const bool addb = (r <= t) && (t < RR);
#pragma unroll
        for (int nt = 0; nt < 2; ++nt) {
            const int j0 = jb + nt * 8 + fc * 2;
            const float* gxp = g_gx + ((size_t)t * MTOT + M) * NTOT + j0;
            float v[NG][2];
#pragma unroll
            for (int g = 0; g < NG; ++g) {
                float2 gxv = *(const float2*)(gxp + g * 256);
                v[g][0] = acc[g][nt][rr * 2] + gxv.x;
                v[g][1] = acc[g][nt][rr * 2 + 1] + gxv.y;
                if (addb) { v[g][0] += Bias[g * 256 + j0]; v[g][1] += Bias[g * 256 + j0 + 1]; }
            }
            const size_t hidx = (size_t)M * HH + j0;
            float2 hro = *(const float2*)&g_hrow[par][hidx];
            float2 hco = *(const float2*)&g_hcol[par][hidx];
            float hr[2], hc[2];
#pragma unroll
            for (int jj = 0; jj < 2; ++jj) {
                float ur = sigmoidf_(v[0][jj]);
                float orr = sigmoidf_(v[1][jj]);
                float uc = sigmoidf_(v[2][jj]);
                float oc = sigmoidf_(v[3][jj]);
                float ir = tanhf(v[4][jj]);
                float ic = tanhf(v[5][jj]);
                float ho = jj ? hro.y : hro.x;
                float co = jj ? hco.y : hco.x;
                hr[jj] = tanhf((1.0f - ur) * ho + ur * ir) * orr;
                hc[jj] = tanhf((1.0f - uc) * co + uc * ic) * oc;
            }
            *(float2*)&g_hrow[wb][hidx] = make_float2(hr[0], hr[1]);
            const int Mr = (((r + 1) & 31) << 6) | b;        // roll(h_col,+1,axis=0)
            *(float2*)&g_hcol[wb][(size_t)Mr * HH + j0] = make_float2(hc[0], hc[1]);

            // next-step Z (bf16 hi/lo)
            __nv_bfloat16 h0 = __float2bfloat16(hr[0]), h1 = __float2bfloat16(hr[1]);
            float l0 = hr[0] - __bfloat162float(h0), l1 = hr[1] - __bfloat162float(h1);
            *(uint32_t*)&g_zh_hi[wb][(size_t)M * KH + j0] = bfpack(hr[0], hr[1]);
            *(uint32_t*)&g_zh_lo[wb][(size_t)M * KH + j0] = bfpack(l0, l1);
            __nv_bfloat16 c0 = __float2bfloat16(hc[0]), c1 = __float2bfloat16(hc[1]);
            float m0c = hc[0] - __bfloat162float(c0), m1c = hc[1] - __bfloat162float(c1);
            *(uint32_t*)&g_zh_hi[wb][(size_t)Mr * KH + 256 + j0] = bfpack(hc[0], hc[1]);
            *(uint32_t*)&g_zh_lo[wb][(size_t)Mr * KH + 256 + j0] = bfpack(m0c, m1c);

            if (layer == 0) {
                const size_t xb = ((size_t)t * MTOT + M) * KH;
                *(uint32_t*)&g_x1_hi[xb + j0] = bfpack(hr[0], hr[1]);
                *(uint32_t*)&g_x1_lo[xb + j0] = bfpack(l0, l1);
                *(uint32_t*)&g_x1_hi[xb + 256 + j0] = bfpack(hc[0], hc[1]);
                *(uint32_t*)&g_x1_lo[xb + 256 + j0] = bfpack(m0c, m1c);
            } else {
                const size_t ob = ((size_t)M * LLEN + t) * 512;
                *(float2*)&dout[ob + j0] = make_float2(hr[0], hr[1]);
                *(float2*)&dout[ob + 256 + j0] = make_float2(hc[0], hc[1]);
            }
            if (t >= RR - 1) {
                const int k = t - (RR - 1);
                if (r == k)
                    *(float2*)&dout[OFF1 + (((size_t)b * 2 + layer) * RR + k) * HH + j0] =
                        make_float2(hr[0], hr[1]);
                if (r == RR - 1)
                    *(float2*)&dout[OFF2 + (((size_t)b * 2 + layer) * RR + k) * HH + j0] =
                        make_float2(hc[0], hc[1]);
            }
        }
    }
}

// ---------------- host ----------------
extern "C" void kernel_launch(void* const* d_in, const int* in_sizes, int n_in,
                              void* d_out, int out_size) {
    (void)in_sizes; (void)n_in; (void)out_size;
    const float* inp  = (const float*)d_in[0];
    const float* Wf   = (const float*)d_in[1];
    const float* Wo   = (const float*)d_in[2];
    const float* Bias = (const float*)d_in[3];
    float* out = (float*)d_out;

    cudaFuncSetAttribute(gemm_k, cudaFuncAttributeMaxDynamicSharedMemorySize, SMEMT);

    prep_w<<<512, 256>>>(Wf, Wo);
    gx0_kernel<<<LLEN * MTOT, 256>>>(inp, Wf);

    dim3 sgrid(MTOT / BM, HH / BJ);          // 16 x 16 = 256 CTAs
    // layer 0
    init_h<<<(MTOT * KH + 255) / 256, 256>>>();
    for (int t = 0; t < LLEN; ++t)
        gemm_k<<<sgrid, 256, SMEMT>>>(0, 0, t, t & 1, Bias, out);
    // batched layer-1 x-contribution (triangle-skipped)
    {
        dim3 bgrid(MTOT / BM, HH / BJ, LLEN);
        gemm_k<<<bgrid, 256, SMEMT>>>(1, 1, 0, 0, Bias, out);
    }
    // layer 1
    init_h<<<(MTOT * KH + 255) / 256, 256>>>();
    for (int t = 0; t < LLEN; ++t)
        gemm_k<<<sgrid, 256, SMEMT>>>(0, 1, t, t & 1, Bias + NTOT, out);
}

// round 6
// speedup vs baseline: 2.7843x; 1.1395x over previous
#include <cuda_runtime.h>
#include <cuda_bf16.h>
#include <math.h>
#include <stdint.h>

// ---------------- problem constants ----------------
#define RR    32
#define LLEN  63
#define HH    256
#define MTOT  2048
#define NG    6
#define KH    512            // sequential K (h_row 256 + h_col 256)
#define NTOT  1536
#define OFF1  66060288ull
#define OFF2  67108864ull

// ---------------- device scratch ----------------
// state is per-layer now (wavefront runs both layers concurrently)
__device__ float g_hrow[2][2][MTOT * HH];            // [layer][buf]
__device__ float g_hcol[2][2][MTOT * HH];
__device__ __nv_bfloat16 g_zh_hi[2][2][MTOT * KH];
__device__ __nv_bfloat16 g_zh_lo[2][2][MTOT * KH];
__device__ __nv_bfloat16 g_x1_hi[(size_t)LLEN * MTOT * KH];
__device__ __nv_bfloat16 g_x1_lo[(size_t)LLEN * MTOT * KH];
__device__ __nv_bfloat16 g_wh_hi[2][NTOT * KH];
__device__ __nv_bfloat16 g_wh_lo[2][NTOT * KH];
__device__ __nv_bfloat16 g_wx_hi[NTOT * KH];
__device__ __nv_bfloat16 g_wx_lo[NTOT * KH];
__device__ float g_gx[(size_t)LLEN * MTOT * NTOT];   // per-step x-contribution of gates

// ---------------- helpers ----------------
__device__ __forceinline__ uint32_t smem_u32(const void* p) {
    uint32_t a;
    asm("{ .reg .u64 t; cvta.to.shared.u64 t, %1; cvt.u32.u64 %0, t; }" : "=r"(a) : "l"(p));
    return a;
}
__device__ __forceinline__ void cp16(uint32_t s, const void* g) {
    asm volatile("cp.async.cg.shared.global [%0], [%1], 16;" :: "r"(s), "l"(g));
}
#define CP_COMMIT() asm volatile("cp.async.commit_group;")
#define CP_WAIT1()  asm volatile("cp.async.wait_group 1;")
#define CP_WAIT0()  asm volatile("cp.async.wait_group 0;")

#define MMA(accp, a, b0, b1) \
    asm volatile("mma.sync.aligned.m16n8k16.row.col.f32.bf16.bf16.f32 " \
        "{%0,%1,%2,%3}, {%4,%5,%6,%7}, {%8,%9}, {%0,%1,%2,%3};" \
        : "+f"((accp)[0]), "+f"((accp)[1]), "+f"((accp)[2]), "+f"((accp)[3]) \
        : "r"((a)[0]), "r"((a)[1]), "r"((a)[2]), "r"((a)[3]), "r"(b0), "r"(b1))

#define LDSM4(r, addr) \
    asm volatile("ldmatrix.sync.aligned.m8n8.x4.shared.b16 {%0,%1,%2,%3}, [%4];" \
        : "=r"((r)[0]), "=r"((r)[1]), "=r"((r)[2]), "=r"((r)[3]) : "r"(addr))

__device__ __forceinline__ float sigmoidf_(float x) { return 1.0f / (1.0f + __expf(-x)); }
__device__ __forceinline__ uint32_t bfpack(float x, float y) {
    __nv_bfloat162 p = __floats2bfloat162_rn(x, y);
    return *reinterpret_cast<uint32_t*>(&p);
}

// ---------------- smem layout (per stage) ----------------
#define BM 128
#define BJ 16                  // j per CTA (x6 gates = 96 N-rows)
#define S_AH 0                 // A hi: 128 rows x 80B = 10240
#define S_AL 10240
#define S_BH 20480             // B hi: 96 rows x 80B = 7680
#define S_BL 28160
#define STAGE 35840
#define NSTAGE 3
#define SMEMT (NSTAGE * STAGE)   // 107520 -> 2 CTAs/SM

// ---------------- prep kernels ----------------
__global__ void prep_w(const float* __restrict__ Wf, const float* __restrict__ Wo) {
    const int N = NTOT * KH;
    for (int i = blockIdx.x * blockDim.x + threadIdx.x; i < 3 * N; i += gridDim.x * blockDim.x) {
        int rgn = i / N, j = i % N;
        int n = j / KH, k = j % KH;
        float v;
        __nv_bfloat16 *dh, *dl;
        if (rgn == 0)      { v = Wf[(size_t)n * 520 + k];        dh = g_wh_hi[0]; dl = g_wh_lo[0]; }
        else if (rgn == 1) { v = Wo[(size_t)n * 1024 + k];       dh = g_wh_hi[1]; dl = g_wh_lo[1]; }
        else               { v = Wo[(size_t)n * 1024 + 512 + k]; dh = g_wx_hi;    dl = g_wx_lo;    }
        __nv_bfloat16 hi = __float2bfloat16(v);
        dh[j] = hi;
        dl[j] = __float2bfloat16(v - __bfloat162float(hi));
    }
}

// layer-0 x-contribution: g_gx[t,M,n] = sum_{k<8} x0(t,M,k) * Wf[n][512+k]  (exact fp32)
__global__ void gx0_kernel(const float* __restrict__ inp, const float* __restrict__ Wf) {
    const int blk = blockIdx.x;                 // t*2048 + M
    const int t = blk >> 11, M = blk & (MTOT - 1);
    const int r = M >> 6, b = M & 63, c = t - r;
    const bool valid = (c >= 0 && c < 32);
    float x[8];
    if (valid) {
#pragma unroll
        for (int k = 0; k < 8; ++k)
            x[k] = inp[(((size_t)b * RR + r) * 32 + c) * 8 + k];
    }
    float* dst = g_gx + (size_t)blk * NTOT;
    for (int n = threadIdx.x; n < NTOT; n += blockDim.x) {
        float s = 0.0f;
        if (valid) {
            const float* w = Wf + (size_t)n * 520 + 512;
#pragma unroll
            for (int k = 0; k < 8; ++k) s += x[k] * w[k];
        }
        dst[n] = s;
    }
}

__global__ void init_all() {
    int i = blockIdx.x * blockDim.x + threadIdx.x;
    if (i < MTOT * KH) {
        __nv_bfloat16 z = __float2bfloat16(0.0f);
        g_zh_hi[0][0][i] = z; g_zh_lo[0][0][i] = z;
        g_zh_hi[1][0][i] = z; g_zh_lo[1][0][i] = z;
        if (i < MTOT * HH) {
            g_hrow[0][0][i] = 0.0f; g_hcol[0][0][i] = 0.0f;
            g_hrow[1][0][i] = 0.0f; g_hcol[1][0][i] = 0.0f;
        }
    }
}

// ---------------- wavefront fused GEMM ----------------
// One launch = round s with three concurrent roles (blockIdx.z):
//   z=0: SEQ layer0 step t=s        (t in [0,62])
//   z=1: BATCH g_gx[t]=X1[t]@Wx^T,  t=s-1 (t in [0,62])
//   z=2: SEQ layer1 step t=s-2      (t in [0,62])
// All cross-role data deps are >=1 launch apart; launches serialize.
__global__ __launch_bounds__(256, 2) void gemm_k(
    int step, const float* __restrict__ BiasAll, float* __restrict__ dout)
{
    const int role = blockIdx.z;
    int t, layer, mode;
    if (role == 0)      { mode = 0; layer = 0; t = step;     if (t > 62) return; }
    else if (role == 1) { mode = 1; layer = 1; t = step - 1; if (t < 0 || t > 62) return; }
    else                { mode = 0; layer = 1; t = step - 2; if (t < 0) return; }
    const int par = t & 1;

    extern __shared__ char sm[];
    const uint32_t sbase = smem_u32(sm);
    const int tid = threadIdx.x;
    const int lane = tid & 31, w = tid >> 5;
    const int m0 = blockIdx.x * BM;
    const int jb = blockIdx.y * BJ;

    // triangle: rows r > t are identically zero (h stays 0, x is in zero-pad)
    const bool skip = (2 * (int)blockIdx.x > t);
    if (mode && skip) return;                // batch: nothing to write

    const __nv_bfloat16 *Ah, *Al, *Wh, *Wl;
    if (mode) {
        Ah = g_x1_hi + (size_t)t * MTOT * KH;
        Al = g_x1_lo + (size_t)t * MTOT * KH;
        Wh = g_wx_hi; Wl = g_wx_lo;
    } else {
        Ah = g_zh_hi[layer][par]; Al = g_zh_lo[layer][par];
        Wh = g_wh_hi[layer]; Wl = g_wh_lo[layer];
    }

    float acc[NG][2][4];
#pragma unroll
    for (int g = 0; g < NG; ++g)
#pragma unroll
        for (int nt = 0; nt < 2; ++nt)
#pragma unroll
            for (int q = 0; q < 4; ++q) acc[g][nt][q] = 0.0f;

    if (!skip) {
        // ---- cp.async coords ----
        const int lr = tid >> 2;        // 0..63
        const int lc = tid & 3;         // 16B chunk in 64B k-slab
        const char* gA0h = (const char*)(Ah + (size_t)(m0 + lr) * KH) + lc * 16;
        const char* gA0l = (const char*)(Al + (size_t)(m0 + lr) * KH) + lc * 16;
        const uint32_t sAoff = lr * 80 + lc * 16;
        const char* gB[3];
        uint32_t sBoff[3];
#pragma unroll
        for (int i = 0; i < 3; ++i) {
            int v = lr + i * 64;                 // 0..191
            int v96 = (v < 96) ? v : v - 96;
            int wrow = (v96 >> 4) * 256 + jb + (v96 & 15);
            const __nv_bfloat16* base = (v < 96) ? Wh : Wl;
            gB[i] = (const char*)(base + (size_t)wrow * KH) + lc * 16;
            sBoff[i] = ((v < 96) ? S_BH : S_BL) + v96 * 80 + lc * 16;
        }

        auto issue = [&](int c, int buf) {
            const uint32_t sb = sbase + buf * STAGE;
            const size_t go = (size_t)c * 64;
            cp16(sb + S_AH + sAoff, gA0h + go);
            cp16(sb + S_AH + sAoff + 64 * 80, gA0h + (size_t)64 * KH * 2 + go);
            cp16(sb + S_AL + sAoff, gA0l + go);
            cp16(sb + S_AL + sAoff + 64 * 80, gA0l + (size_t)64 * KH * 2 + go);
#pragma unroll
            for (int i = 0; i < 3; ++i) cp16(sb + sBoff[i], gB[i] + go);
            CP_COMMIT();
        };

        // ---- ldmatrix lane coords ----
        const int aRow = (lane & 7) + ((lane >> 3) & 1) * 8;
        const int aKoff = ((lane >> 4) & 1) * 16;
        const int bRow = (lane & 7) + (((lane >> 4) & 1) ? 8 : 0);
        const int bKoff = ((lane >> 3) & 1) * 16;
        const uint32_t aBase = (w * 16 + aRow) * 80 + aKoff;
        const uint32_t bBase = bRow * 80 + bKoff;

        auto compute = [&](int buf) {
            const uint32_t S = sbase + buf * STAGE;
#pragma unroll
            for (int h = 0; h < 2; ++h) {
                uint32_t ah[4], al[4];
                uint32_t aAddr = S + S_AH + aBase + h * 32;
                LDSM4(ah, aAddr);
                LDSM4(al, aAddr + (S_AL - S_AH));
#pragma unroll
                for (int g = 0; g < NG; ++g) {
                    uint32_t bh[4], bl[4];
                    uint32_t bAddr = S + S_BH + g * 16 * 80 + bBase + h * 32;
                    LDSM4(bh, bAddr);
                    LDSM4(bl, bAddr + (S_BL - S_BH));
                    MMA(acc[g][0], ah, bh[0], bh[1]);
                    MMA(acc[g][1], ah, bh[2], bh[3]);
                    MMA(acc[g][0], ah, bl[0], bl[1]);
                    MMA(acc[g][1], ah, bl[2], bl[3]);
                    MMA(acc[g][0], al, bh[0], bh[1]);
                    MMA(acc[g][1], al, bh[2], bh[3]);
                }
            }
        };

        // ---- 3-stage pipelined K loop ----
        issue(0, 0);
        issue(1, 1);
#pragma unroll 1
        for (int c = 0; c < 16; ++c) {
            if (c < 15) CP_WAIT1(); else CP_WAIT0();
            __syncthreads();
            if (c < 14) issue(c + 2, (c + 2) % NSTAGE);
            compute(c % NSTAGE);
        }
    }

    const int fr = lane >> 2, fc = lane & 3;

    // ---- epilogue ----
    if (mode) {
#pragma unroll
        for (int rr = 0; rr < 2; ++rr) {
            const int Ml = w * 16 + rr * 8 + fr;
            float* row = g_gx + ((size_t)t * MTOT + m0 + Ml) * NTOT;
#pragma unroll
            for (int nt = 0; nt < 2; ++nt) {
                const int j0 = jb + nt * 8 + fc * 2;
#pragma unroll
                for (int g = 0; g < NG; ++g)
                    *(float2*)(row + g * 256 + j0) =
                        make_float2(acc[g][nt][rr * 2], acc[g][nt][rr * 2 + 1]);
            }
        }
        return;
    }

    // SEQ: fused pointwise (runs for skip blocks too -> writes the required zeros)
    const float* Bias = BiasAll + layer * NTOT;
    const int wb = par ^ 1;
    const float* hrow_r = g_hrow[layer][par];
    const float* hcol_r = g_hcol[layer][par];
    float* hrow_w = g_hrow[layer][wb];
    float* hcol_w = g_hcol[layer][wb];
#pragma unroll
    for (int rr = 0; rr < 2; ++rr) {
        const int M = m0 + w * 16 + rr * 8 + fr;
        const int r = M >> 6, b = M & 63;
        const bool addb = (r <= t) && (t < RR);
#pragma unroll
        for (int nt = 0; nt < 2; ++nt) {
            const int j0 = jb + nt * 8 + fc * 2;
            const float* gxp = g_gx + ((size_t)t * MTOT + M) * NTOT + j0;
            float v[NG][2];
#pragma unroll
            for (int g = 0; g < NG; ++g) {
                float2 gxv = *(const float2*)(gxp + g * 256);
                v[g][0] = acc[g][nt][rr * 2] + gxv.x;
                v[g][1] = acc[g][nt][rr * 2 + 1] + gxv.y;
                if (addb) { v[g][0] += Bias[g * 256 + j0]; v[g][1] += Bias[g * 256 + j0 + 1]; }
            }
            const size_t hidx = (size_t)M * HH + j0;
            float2 hro = *(const float2*)&hrow_r[hidx];
            float2 hco = *(const float2*)&hcol_r[hidx];
            float hr[2], hc[2];
#pragma unroll
            for (int jj = 0; jj < 2; ++jj) {
                float ur = sigmoidf_(v[0][jj]);
                float orr = sigmoidf_(v[1][jj]);
                float uc = sigmoidf_(v[2][jj]);
                float oc = sigmoidf_(v[3][jj]);
                float ir = tanhf(v[4][jj]);
                float ic = tanhf(v[5][jj]);
                float ho = jj ? hro.y : hro.x;
                float co = jj ? hco.y : hco.x;
                hr[jj] = tanhf((1.0f - ur) * ho + ur * ir) * orr;
                hc[jj] = tanhf((1.0f - uc) * co + uc * ic) * oc;
            }
            *(float2*)&hrow_w[hidx] = make_float2(hr[0], hr[1]);
            const int Mr = (((r + 1) & 31) << 6) | b;        // roll(h_col,+1,axis=0)
            *(float2*)&hcol_w[(size_t)Mr * HH + j0] = make_float2(hc[0], hc[1]);

            // next-step Z (bf16 hi/lo)
            __nv_bfloat16 h0 = __float2bfloat16(hr[0]), h1 = __float2bfloat16(hr[1]);
            float l0 = hr[0] - __bfloat162float(h0), l1 = hr[1] - __bfloat162float(h1);
            *(uint32_t*)&g_zh_hi[layer][wb][(size_t)M * KH + j0] = bfpack(hr[0], hr[1]);
            *(uint32_t*)&g_zh_lo[layer][wb][(size_t)M * KH + j0] = bfpack(l0, l1);
            __nv_bfloat16 c0 = __float2bfloat16(hc[0]), c1 = __float2bfloat16(hc[1]);
            float m0c = hc[0] - __bfloat162float(c0), m1c = hc[1] - __bfloat162float(c1);
            *(uint32_t*)&g_zh_hi[layer][wb][(size_t)Mr * KH + 256 + j0] = bfpack(hc[0], hc[1]);
            *(uint32_t*)&g_zh_lo[layer][wb][(size_t)Mr * KH + 256 + j0] = bfpack(m0c, m1c);

            if (layer == 0) {
                const size_t xb = ((size_t)t * MTOT + M) * KH;
                *(uint32_t*)&g_x1_hi[xb + j0] = bfpack(hr[0], hr[1]);
                *(uint32_t*)&g_x1_lo[xb + j0] = bfpack(l0, l1);
                *(uint32_t*)&g_x1_hi[xb + 256 + j0] = bfpack(hc[0], hc[1]);
                *(uint32_t*)&g_x1_lo[xb + 256 + j0] = bfpack(m0c, m1c);
            } else {
                const size_t ob = ((size_t)M * LLEN + t) * 512;
                *(float2*)&dout[ob + j0] = make_float2(hr[0], hr[1]);
                *(float2*)&dout[ob + 256 + j0] = make_float2(hc[0], hc[1]);
            }
            if (t >= RR - 1) {
                const int k = t - (RR - 1);
                if (r == k)
                    *(float2*)&dout[OFF1 + (((size_t)b * 2 + layer) * RR + k) * HH + j0] =
                        make_float2(hr[0], hr[1]);
                if (r == RR - 1)
                    *(float2*)&dout[OFF2 + (((size_t)b * 2 + layer) * RR + k) * HH + j0] =
                        make_float2(hc[0], hc[1]);
            }
        }
    }
}

// ---------------- host ----------------
extern "C" void kernel_launch(void* const* d_in, const int* in_sizes, int n_in,
                              void* d_out, int out_size) {
    (void)in_sizes; (void)n_in; (void)out_size;
    const float* inp  = (const float*)d_in[0];
    const float* Wf   = (const float*)d_in[1];
    const float* Wo   = (const float*)d_in[2];
    const float* Bias = (const float*)d_in[3];
    float* out = (float*)d_out;

    cudaFuncSetAttribute(gemm_k, cudaFuncAttributeMaxDynamicSharedMemorySize, SMEMT);

    prep_w<<<512, 256>>>(Wf, Wo);
    gx0_kernel<<<LLEN * MTOT, 256>>>(inp, Wf);
    init_all<<<(MTOT * KH + 255) / 256, 256>>>();

    // wavefront: round s = layer0 step s | batch gx(s-1) | layer1 step s-2
    dim3 wgrid(MTOT / BM, HH / BJ, 3);       // 16 x 16 x 3
    for (int s = 0; s <= 64; ++s)
        gemm_k<<<wgrid, 256, SMEMT>>>(s, Bias, out);
}

// round 8
// speedup vs baseline: 3.0727x; 1.1036x over previous
#include <cuda_runtime.h>
#include <cuda_bf16.h>
#include <math.h>
#include <stdint.h>

// ---------------- problem constants ----------------
#define RR    32
#define LLEN  63
#define HH    256
#define MTOT  2048
#define NG    6
#define NTOT  1536
#define KW0   576            // layer0 A/W width per plane: 512 h + 64 x-pad (8 real)
#define KW1   1024           // layer1: 512 h + 512 x1
#define NC0   18             // k32 chunks
#define NC1   32
#define OFF1  66060288ull
#define OFF2  67108864ull

// ---------------- device scratch ----------------
// z-state rows: 1024 bf16 = [hi 512 | lo 512]; hi = [h_row 256 | h_col 256]
__device__ __nv_bfloat16 g_zh[2][2][MTOT * 1024];                 // [layer][buf]
__device__ __nv_bfloat16 g_x1[(size_t)LLEN * MTOT * 1024];        // layer1 x rows [hi512|lo512]
__device__ __nv_bfloat16 g_x0[LLEN * MTOT * 128];                 // layer0 x rows [hi64|lo64]
__device__ __nv_bfloat16 g_w0h[NTOT * KW0], g_w0l[NTOT * KW0];
__device__ __nv_bfloat16 g_w1h[NTOT * KW1], g_w1l[NTOT * KW1];

// ---------------- helpers ----------------
__device__ __forceinline__ uint32_t smem_u32(const void* p) {
    uint32_t a;
    asm("{ .reg .u64 t; cvta.to.shared.u64 t, %1; cvt.u32.u64 %0, t; }" : "=r"(a) : "l"(p));
    return a;
}
__device__ __forceinline__ void cp16(uint32_t s, const void* g) {
    asm volatile("cp.async.cg.shared.global [%0], [%1], 16;" :: "r"(s), "l"(g));
}
#define CP_COMMIT() asm volatile("cp.async.commit_group;")
#define CP_WAIT1()  asm volatile("cp.async.wait_group 1;")
#define CP_WAIT0()  asm volatile("cp.async.wait_group 0;")

#define MMA(accp, a, b0, b1) \
    asm volatile("mma.sync.aligned.m16n8k16.row.col.f32.bf16.bf16.f32 " \
        "{%0,%1,%2,%3}, {%4,%5,%6,%7}, {%8,%9}, {%0,%1,%2,%3};" \
        : "+f"((accp)[0]), "+f"((accp)[1]), "+f"((accp)[2]), "+f"((accp)[3]) \
        : "r"((a)[0]), "r"((a)[1]), "r"((a)[2]), "r"((a)[3]), "r"(b0), "r"(b1))

#define LDSM4(r, addr) \
    asm volatile("ldmatrix.sync.aligned.m8n8.x4.shared.b16 {%0,%1,%2,%3}, [%4];" \
        : "=r"((r)[0]), "=r"((r)[1]), "=r"((r)[2]), "=r"((r)[3]) : "r"(addr))

__device__ __forceinline__ float sigmoidf_(float x) { return 1.0f / (1.0f + __expf(-x)); }
__device__ __forceinline__ uint32_t bfpack(float x, float y) {
    __nv_bfloat162 p = __floats2bfloat162_rn(x, y);
    return *reinterpret_cast<uint32_t*>(&p);
}

// ---------------- smem layout (per stage): k32 chunks, rows padded to 80B ----------------
#define BM 128
#define BJ 16
#define S_AH 0                 // A hi: 128 rows x 80B = 10240
#define S_AL 10240
#define S_BH 20480             // B hi: 96 rows x 80B = 7680
#define S_BL 28160
#define STAGE 35840
#define NSTAGE 3
#define SMEMT (NSTAGE * STAGE) // 107520 -> 2 CTAs/SM

// ---------------- prep kernels ----------------
__global__ void prep_w(const float* __restrict__ Wf, const float* __restrict__ Wo) {
    const int N0 = NTOT * KW0, N1 = NTOT * KW1;
    for (int i = blockIdx.x * blockDim.x + threadIdx.x; i < N0 + N1; i += gridDim.x * blockDim.x) {
        float v;
        __nv_bfloat16 *dh, *dl;
        int j;
        if (i < N0) {
            j = i;
            int n = j / KW0, k = j % KW0;
            v = (k < 520) ? Wf[(size_t)n * 520 + k] : 0.0f;
            dh = g_w0h; dl = g_w0l;
        } else {
            j = i - N0;
            v = Wo[j];                    // [1536][1024] contiguous
            dh = g_w1h; dl = g_w1l;
        }
        __nv_bfloat16 hi = __float2bfloat16(v);
        dh[j] = hi;
        dl[j] = __float2bfloat16(v - __bfloat162float(hi));
    }
}

// x0 planes: g_x0[t][M][128] = [hi 64 | lo 64]; real features at cols 0..7
__global__ void prep_x0(const float* __restrict__ inp) {
    const int TOT = LLEN * MTOT * 128;
    for (int i = blockIdx.x * blockDim.x + threadIdx.x; i < TOT; i += gridDim.x * blockDim.x) {
        int col = i & 127;
        int M = (i >> 7) & (MTOT - 1);
        int t = i >> 18;
        int k = col & 63;
        int r = M >> 6, b = M & 63, c = t - r;
        float v = 0.0f;
        if (k < 8 && c >= 0 && c < 32)
            v = inp[(((size_t)b * RR + r) * 32 + c) * 8 + k];
        __nv_bfloat16 hi = __float2bfloat16(v);
        g_x0[i] = (col < 64) ? hi : __float2bfloat16(v - __bfloat162float(hi));
    }
}

__global__ void init_all() {
    int i = blockIdx.x * blockDim.x + threadIdx.x;
    if (i < MTOT * 1024) {
        __nv_bfloat16 z = __float2bfloat16(0.0f);
        g_zh[0][0][i] = z;
        g_zh[1][0][i] = z;
    }
}

// ---------------- wavefront fused GEMM + pointwise ----------------
// round s, roles (blockIdx.z): z=0: layer0 t=s ; z=1: layer1 t=s-1
__global__ __launch_bounds__(256, 2) void gemm_k(
    int step, const float* __restrict__ BiasAll, float* __restrict__ dout)
{
    const int layer = blockIdx.z;
    const int t = step - layer;
    if (t < 0 || t > 62) return;
    const int par = t & 1;
    const int nc = layer ? NC1 : NC0;
    const int kw = layer ? KW1 : KW0;

    extern __shared__ char sm[];
    const uint32_t sbase = smem_u32(sm);
    const int tid = threadIdx.x;
    const int lane = tid & 31, w = tid >> 5;
    const int m0 = blockIdx.x * BM;
    const int jb = blockIdx.y * BJ;

    const bool skip = (2 * (int)blockIdx.x > t);   // rows r > t identically zero

    float acc[NG][2][4];
#pragma unroll
    for (int g = 0; g < NG; ++g)
#pragma unroll
        for (int nt = 0; nt < 2; ++nt)
#pragma unroll
            for (int q = 0; q < 4; ++q) acc[g][nt][q] = 0.0f;

    if (!skip) {
        const __nv_bfloat16* Wh = layer ? g_w1h : g_w0h;
        const __nv_bfloat16* Wl = layer ? g_w1l : g_w0l;

        // ---- cp.async coords ----
        const int lr = tid >> 2;        // 0..63
        const int lc = tid & 3;         // 16B piece
        // z-state rows: stride 2048B, hi at +0, lo at +1024
        const char* pZ = (const char*)g_zh[layer][par] + (size_t)(m0 + lr) * 2048 + lc * 16;
        // x rows
        const int xstride = layer ? 2048 : 256;     // bytes per row
        const int xlo = layer ? 1024 : 128;         // lo-plane byte offset
        const char* pX = (layer ? (const char*)g_x1 + ((size_t)t * MTOT) * 2048
                                : (const char*)g_x0 + ((size_t)t * MTOT) * 256)
                         + (size_t)(m0 + lr) * xstride + lc * 16;
        const int xs2 = 64 * xstride;               // second-A-row offset in x region
        const uint32_t sAoff = lr * 80 + lc * 16;

        const char* gB[3];
        uint32_t sBoff[3];
#pragma unroll
        for (int i = 0; i < 3; ++i) {
            int v = lr + i * 64;                 // 0..191 (96 hi rows, 96 lo rows)
            int v96 = (v < 96) ? v : v - 96;
            int wrow = (v96 >> 4) * 256 + jb + (v96 & 15);
            const __nv_bfloat16* base = (v < 96) ? Wh : Wl;
            gB[i] = (const char*)(base + (size_t)wrow * kw) + lc * 16;
            sBoff[i] = ((v < 96) ? S_BH : S_BL) + v96 * 80 + lc * 16;
        }

        auto issue = [&](int c, int buf) {
            const uint32_t sb = sbase + buf * STAGE;
            const char *ah, *al;
            int a2;                                  // second-row offset
            if (c < 16) {
                ah = pZ + (size_t)c * 64;
                al = ah + 1024;
                a2 = 64 * 2048;
            } else {
                ah = pX + (size_t)(c - 16) * 64;
                al = ah + xlo;
                a2 = xs2;
            }
            cp16(sb + S_AH + sAoff, ah);
            cp16(sb + S_AH + sAoff + 64 * 80, ah + a2);
            cp16(sb + S_AL + sAoff, al);
            cp16(sb + S_AL + sAoff + 64 * 80, al + a2);
            const size_t go = (size_t)c * 64;
#pragma unroll
            for (int i = 0; i < 3; ++i) cp16(sb + sBoff[i], gB[i] + go);
            CP_COMMIT();
        };

        // ---- ldmatrix lane coords (warp = m16 x n16) ----
        const int aRow = (lane & 7) + ((lane >> 3) & 1) * 8;
        const int aKoff = ((lane >> 4) & 1) * 16;
        const int bRow = (lane & 7) + (((lane >> 4) & 1) ? 8 : 0);
        const int bKoff = ((lane >> 3) & 1) * 16;
        const uint32_t aBase = (w * 16 + aRow) * 80 + aKoff;
        const uint32_t bBase = bRow * 80 + bKoff;

        auto compute = [&](int buf) {
            const uint32_t S = sbase + buf * STAGE;
#pragma unroll
            for (int h = 0; h < 2; ++h) {
                uint32_t ah[4], al[4];
                uint32_t aAddr = S + S_AH + aBase + h * 32;
                LDSM4(ah, aAddr);
                LDSM4(al, aAddr + (S_AL - S_AH));
#pragma unroll
                for (int g = 0; g < NG; ++g) {
                    uint32_t bh[4], bl[4];
                    uint32_t bAddr = S + S_BH + g * 16 * 80 + bBase + h * 32;
                    LDSM4(bh, bAddr);
                    LDSM4(bl, bAddr + (S_BL - S_BH));
                    MMA(acc[g][0], ah, bh[0], bh[1]);
                    MMA(acc[g][1], ah, bh[2], bh[3]);
                    MMA(acc[g][0], ah, bl[0], bl[1]);
                    MMA(acc[g][1], ah, bl[2], bl[3]);
                    MMA(acc[g][0], al, bh[0], bh[1]);
                    MMA(acc[g][1], al, bh[2], bh[3]);
                }
            }
        };

        // ---- 3-stage pipelined K loop, one syncthreads per chunk ----
        issue(0, 0);
        issue(1, 1);
#pragma unroll 1
        for (int c = 0; c < nc; ++c) {
            if (c < nc - 1) CP_WAIT1(); else CP_WAIT0();
            __syncthreads();
            if (c + 2 < nc) issue(c + 2, (c + 2) % NSTAGE);
            compute(c % NSTAGE);
        }
    }

    const int fr = lane >> 2, fc = lane & 3;

    // ---- fused pointwise epilogue (runs for skip blocks too -> required zeros) ----
    const float* Bias = BiasAll + layer * NTOT;
    const int wb = par ^ 1;
    const __nv_bfloat16* zr = g_zh[layer][par];
    __nv_bfloat16* zw = g_zh[layer][wb];
#pragma unroll
    for (int rr = 0; rr < 2; ++rr) {
        const int M = m0 + w * 16 + rr * 8 + fr;
        const int r = M >> 6, b = M & 63;
        const bool addb = (r <= t) && (t < RR);
#pragma unroll
        for (int nt = 0; nt < 2; ++nt) {
            const int j0 = jb + nt * 8 + fc * 2;
            float v[NG][2];
#pragma unroll
            for (int g = 0; g < NG; ++g) {
                v[g][0] = acc[g][nt][rr * 2];
                v[g][1] = acc[g][nt][rr * 2 + 1];
                if (addb) { v[g][0] += Bias[g * 256 + j0]; v[g][1] += Bias[g * 256 + j0 + 1]; }
            }
            // h_old from z-planes: h = hi + lo (exact reconstruction of carried state)
            const size_t zi = (size_t)M * 1024;
            __nv_bfloat162 rh = *(const __nv_bfloat162*)&zr[zi + j0];
            __nv_bfloat162 rl = *(const __nv_bfloat162*)&zr[zi + 512 + j0];
            __nv_bfloat162 ch = *(const __nv_bfloat162*)&zr[zi + 256 + j0];
            __nv_bfloat162 cl = *(const __nv_bfloat162*)&zr[zi + 768 + j0];
            float hro[2] = { __low2float(rh) + __low2float(rl), __high2float(rh) + __high2float(rl) };
            float hco[2] = { __low2float(ch) + __low2float(cl), __high2float(ch) + __high2float(cl) };
            float hr[2], hc[2];
#pragma unroll
            for (int jj = 0; jj < 2; ++jj) {
                float ur = sigmoidf_(v[0][jj]);
                float orr = sigmoidf_(v[1][jj]);
                float uc = sigmoidf_(v[2][jj]);
                float oc = sigmoidf_(v[3][jj]);
                float ir = tanhf(v[4][jj]);
                float ic = tanhf(v[5][jj]);
                hr[jj] = tanhf((1.0f - ur) * hro[jj] + ur * ir) * orr;
                hc[jj] = tanhf((1.0f - uc) * hco[jj] + uc * ic) * oc;
            }
            // write next-step z-state: h_row at M, h_col at rolled index Mr
            const int Mr = (((r + 1) & 31) << 6) | b;
            float lr0 = hr[0], lr1 = hr[1], lc0 = hc[0], lc1 = hc[1];
            uint32_t hrhi = bfpack(hr[0], hr[1]);
            float r0f = hr[0] - __bfloat162float(__float2bfloat16(hr[0]));
            float r1f = hr[1] - __bfloat162float(__float2bfloat16(hr[1]));
            uint32_t hrlo = bfpack(r0f, r1f);
            uint32_t hchi = bfpack(hc[0], hc[1]);
            float c0f = hc[0] - __bfloat162float(__float2bfloat16(hc[0]));
            float c1f = hc[1] - __bfloat162float(__float2bfloat16(hc[1]));
            uint32_t hclo = bfpack(c0f, c1f);
            (void)lr0; (void)lr1; (void)lc0; (void)lc1;

            *(uint32_t*)&zw[(size_t)M * 1024 + j0] = hrhi;
            *(uint32_t*)&zw[(size_t)M * 1024 + 512 + j0] = hrlo;
            *(uint32_t*)&zw[(size_t)Mr * 1024 + 256 + j0] = hchi;
            *(uint32_t*)&zw[(size_t)Mr * 1024 + 768 + j0] = hclo;

            if (layer == 0) {
                // layer-1 x input at step t (un-rolled concat)
                const size_t xb = ((size_t)t * MTOT + M) * 1024;
                *(uint32_t*)&g_x1[xb + j0] = hrhi;
                *(uint32_t*)&g_x1[xb + 512 + j0] = hrlo;
                *(uint32_t*)&g_x1[xb + 256 + j0] = hchi;
                *(uint32_t*)&g_x1[xb + 768 + j0] = hclo;
            } else {
                const size_t ob = ((size_t)M * LLEN + t) * 512;
                *(float2*)&dout[ob + j0] = make_float2(hr[0], hr[1]);
                *(float2*)&dout[ob + 256 + j0] = make_float2(hc[0], hc[1]);
            }
            if (t >= RR - 1) {
                const int k = t - (RR - 1);
                if (r == k)
                    *(float2*)&dout[OFF1 + (((size_t)b * 2 + layer) * RR + k) * HH + j0] =
                        make_float2(hr[0], hr[1]);
                if (r == RR - 1)
                    *(float2*)&dout[OFF2 + (((size_t)b * 2 + layer) * RR + k) * HH + j0] =
                        make_float2(hc[0], hc[1]);
            }
        }
    }
}

// ---------------- host ----------------
extern "C" void kernel_launch(void* const* d_in, const int* in_sizes, int n_in,
                              void* d_out, int out_size) {
    (void)in_sizes; (void)n_in; (void)out_size;
    const float* inp  = (const float*)d_in[0];
    const float* Wf   = (const float*)d_in[1];
    const float* Wo   = (const float*)d_in[2];
    const float* Bias = (const float*)d_in[3];
    float* out = (float*)d_out;

    cudaFuncSetAttribute(gemm_k, cudaFuncAttributeMaxDynamicSharedMemorySize, SMEMT);

    prep_w<<<512, 256>>>(Wf, Wo);
    prep_x0<<<1024, 256>>>(inp);
    init_all<<<(MTOT * 1024 + 255) / 256, 256>>>();

    // wavefront: round s = layer0 step s | layer1 step s-1
    dim3 wgrid(MTOT / BM, HH / BJ, 2);       // 16 x 16 x 2
    for (int s = 0; s <= 63; ++s)
        gemm_k<<<wgrid, 256, SMEMT>>>(s, Bias, out);
}

// round 9
// speedup vs baseline: 6.0973x; 1.9844x over previous
#include <cuda_runtime.h>
#include <cuda_fp16.h>
#include <math.h>
#include <stdint.h>

// ---------------- problem constants ----------------
#define RR    32
#define LLEN  63
#define HH    256
#define MTOT  2048
#define NG    6
#define NTOT  1536
#define KW0   576            // layer0 K: 512 h + 64 x-pad (8 real)
#define KW1   1024           // layer1 K: 512 h + 512 x1
#define NC0   18             // k32 chunks
#define NC1   32
#define OFF1  66060288ull
#define OFF2  67108864ull

// ---------------- device scratch ----------------
// z-state rows: 1024 fp16 = [hi 512 | lo 512]; hi = [h_row 256 | h_col 256]
// GEMM reads hi only; lo is for exact state reconstruction in the pointwise.
__device__ __half g_zh[2][2][MTOT * 1024];                 // [layer][buf]
__device__ __half g_x1[(size_t)LLEN * MTOT * 512];         // layer1 x rows (hi only)
__device__ __half g_x0[LLEN * MTOT * 64];                  // layer0 x rows (hi only)
__device__ __half g_w0[NTOT * KW0];
__device__ __half g_w1[NTOT * KW1];

// ---------------- helpers ----------------
__device__ __forceinline__ uint32_t smem_u32(const void* p) {
    uint32_t a;
    asm("{ .reg .u64 t; cvta.to.shared.u64 t, %1; cvt.u32.u64 %0, t; }" : "=r"(a) : "l"(p));
    return a;
}
__device__ __forceinline__ void cp16(uint32_t s, const void* g) {
    asm volatile("cp.async.cg.shared.global [%0], [%1], 16;" :: "r"(s), "l"(g));
}
#define CP_COMMIT() asm volatile("cp.async.commit_group;")
#define CP_WAIT1()  asm volatile("cp.async.wait_group 1;")
#define CP_WAIT0()  asm volatile("cp.async.wait_group 0;")

#define MMA(accp, a, b0, b1) \
    asm volatile("mma.sync.aligned.m16n8k16.row.col.f32.f16.f16.f32 " \
        "{%0,%1,%2,%3}, {%4,%5,%6,%7}, {%8,%9}, {%0,%1,%2,%3};" \
        : "+f"((accp)[0]), "+f"((accp)[1]), "+f"((accp)[2]), "+f"((accp)[3]) \
        : "r"((a)[0]), "r"((a)[1]), "r"((a)[2]), "r"((a)[3]), "r"(b0), "r"(b1))

#define LDSM4(r, addr) \
    asm volatile("ldmatrix.sync.aligned.m8n8.x4.shared.b16 {%0,%1,%2,%3}, [%4];" \
        : "=r"((r)[0]), "=r"((r)[1]), "=r"((r)[2]), "=r"((r)[3]) : "r"(addr))

__device__ __forceinline__ float sigmoidf_(float x) { return 1.0f / (1.0f + __expf(-x)); }
__device__ __forceinline__ uint32_t hpack(float x, float y) {
    __half2 p = __floats2half2_rn(x, y);
    return *reinterpret_cast<uint32_t*>(&p);
}

// ---------------- smem layout (per stage): k32 chunks, rows padded to 80B ----------------
#define BM 128
#define BJ 16
#define S_A  0                 // A: 128 rows x 80B = 10240
#define S_B  10240             // B: 96 rows x 80B = 7680
#define STAGE 17920
#define NSTAGE 3
#define SMEMT (NSTAGE * STAGE) // 53760 -> 2 CTAs/SM (reg-limited)

// ---------------- prep kernels ----------------
__global__ void prep_w(const float* __restrict__ Wf, const float* __restrict__ Wo) {
    const int N0 = NTOT * KW0, N1 = NTOT * KW1;
    for (int i = blockIdx.x * blockDim.x + threadIdx.x; i < N0 + N1; i += gridDim.x * blockDim.x) {
        if (i < N0) {
            int n = i / KW0, k = i % KW0;
            float v = (k < 520) ? Wf[(size_t)n * 520 + k] : 0.0f;
            g_w0[i] = __float2half_rn(v);
        } else {
            g_w1[i - N0] = __float2half_rn(Wo[i - N0]);   // [1536][1024] contiguous
        }
    }
}

// x0: g_x0[t][M][64]; real features at cols 0..7
__global__ void prep_x0(const float* __restrict__ inp) {
    const int TOT = LLEN * MTOT * 64;
    for (int i = blockIdx.x * blockDim.x + threadIdx.x; i < TOT; i += gridDim.x * blockDim.x) {
        int k = i & 63;
        int M = (i >> 6) & (MTOT - 1);
        int t = i >> 17;
        int r = M >> 6, b = M & 63, c = t - r;
        float v = 0.0f;
        if (k < 8 && c >= 0 && c < 32)
            v = inp[(((size_t)b * RR + r) * 32 + c) * 8 + k];
        g_x0[i] = __float2half_rn(v);
    }
}

__global__ void init_all() {
    int i = blockIdx.x * blockDim.x + threadIdx.x;
    if (i < MTOT * 1024) {
        __half z = __float2half_rn(0.0f);
        g_zh[0][0][i] = z;
        g_zh[1][0][i] = z;
    }
}

// ---------------- wavefront fused GEMM + pointwise ----------------
// round s, roles (blockIdx.z): z=0: layer0 t=s ; z=1: layer1 t=s-1
__global__ __launch_bounds__(256, 2) void gemm_k(
    int step, const float* __restrict__ BiasAll, float* __restrict__ dout)
{
    const int layer = blockIdx.z;
    const int t = step - layer;
    if (t < 0 || t > 62) return;
    const int par = t & 1;
    const int nc = layer ? NC1 : NC0;
    const int kw = layer ? KW1 : KW0;

    extern __shared__ char sm[];
    const uint32_t sbase = smem_u32(sm);
    const int tid = threadIdx.x;
    const int lane = tid & 31, w = tid >> 5;
    const int m0 = blockIdx.x * BM;
    const int jb = blockIdx.y * BJ;

    const bool skip = (2 * (int)blockIdx.x > t);   // rows r > t identically zero

    float acc[NG][2][4];
#pragma unroll
    for (int g = 0; g < NG; ++g)
#pragma unroll
        for (int nt = 0; nt < 2; ++nt)
#pragma unroll
            for (int q = 0; q < 4; ++q) acc[g][nt][q] = 0.0f;

    if (!skip) {
        const __half* W = layer ? g_w1 : g_w0;

        // ---- cp.async coords ----
        const int lr = tid >> 2;        // 0..63
        const int lc = tid & 3;         // 16B piece of the 64B chunk-row
        // z rows: 2048B stride; hi plane = first 1024B (16 chunks of 64B)
        const char* pZ = (const char*)g_zh[layer][par] + (size_t)(m0 + lr) * 2048 + lc * 16;
        const int xstride = layer ? 1024 : 128;     // bytes per x row
        const char* pX = (layer ? (const char*)g_x1 + ((size_t)t * MTOT) * 1024
                                : (const char*)g_x0 + ((size_t)t * MTOT) * 128)
                         + (size_t)(m0 + lr) * xstride + lc * 16;
        const uint32_t sAoff = lr * 80 + lc * 16;

        // B: 96 rows; stream0 = row lr, stream1 = row 64+lr (lr<32 only)
        int wr0 = (lr >> 4) * 256 + jb + (lr & 15);
        int v1 = 64 + lr;
        int wr1 = (v1 >> 4) * 256 + jb + (v1 & 15);
        const char* gB0 = (const char*)(W + (size_t)wr0 * kw) + lc * 16;
        const char* gB1 = (const char*)(W + (size_t)wr1 * kw) + lc * 16;
        const uint32_t sB0 = S_B + lr * 80 + lc * 16;
        const uint32_t sB1 = S_B + v1 * 80 + lc * 16;
        const bool doB1 = (lr < 32);

        auto issue = [&](int c, int buf) {
            const uint32_t sb = sbase + buf * STAGE;
            const char* ah;
            int a2;
            if (c < 16) { ah = pZ + (size_t)c * 64; a2 = 64 * 2048; }
            else        { ah = pX + (size_t)(c - 16) * 64; a2 = 64 * xstride; }
            cp16(sb + S_A + sAoff, ah);
            cp16(sb + S_A + sAoff + 64 * 80, ah + a2);
            const size_t go = (size_t)c * 64;
            cp16(sb + sB0, gB0 + go);
            if (doB1) cp16(sb + sB1, gB1 + go);
            CP_COMMIT();
        };

        // ---- ldmatrix lane coords (warp = m16 x n16) ----
        const int aRow = (lane & 7) + ((lane >> 3) & 1) * 8;
        const int aKoff = ((lane >> 4) & 1) * 16;
        const int bRow = (lane & 7) + (((lane >> 4) & 1) ? 8 : 0);
        const int bKoff = ((lane >> 3) & 1) * 16;
        const uint32_t aBase = (w * 16 + aRow) * 80 + aKoff;
        const uint32_t bBase = bRow * 80 + bKoff;

        auto compute = [&](int buf) {
            const uint32_t S = sbase + buf * STAGE;
#pragma unroll
            for (int h = 0; h < 2; ++h) {
                uint32_t a[4];
                LDSM4(a, S + S_A + aBase + h * 32);
#pragma unroll
                for (int g = 0; g < NG; ++g) {
                    uint32_t b[4];
                    LDSM4(b, S + S_B + g * 16 * 80 + bBase + h * 32);
                    MMA(acc[g][0], a, b[0], b[1]);
                    MMA(acc[g][1], a, b[2], b[3]);
                }
            }
        };

        // ---- 3-stage pipelined K loop, one syncthreads per chunk ----
        issue(0, 0);
        issue(1, 1);
#pragma unroll 1
        for (int c = 0; c < nc; ++c) {
            if (c < nc - 1) CP_WAIT1(); else CP_WAIT0();
            __syncthreads();
            if (c + 2 < nc) issue(c + 2, (c + 2) % NSTAGE);
            compute(c % NSTAGE);
        }
    }

    const int fr = lane >> 2, fc = lane & 3;

    // ---- fused pointwise epilogue (skip blocks too -> required zeros) ----
    const float* Bias = BiasAll + layer * NTOT;
    const int wb = par ^ 1;
    const __half* zr = g_zh[layer][par];
    __half* zw = g_zh[layer][wb];
#pragma unroll
    for (int rr = 0; rr < 2; ++rr) {
        const int M = m0 + w * 16 + rr * 8 + fr;
        const int r = M >> 6, b = M & 63;
        const bool addb = (r <= t) && (t < RR);
#pragma unroll
        for (int nt = 0; nt < 2; ++nt) {
            const int j0 = jb + nt * 8 + fc * 2;
            float v[NG][2];
#pragma unroll
            for (int g = 0; g < NG; ++g) {
                v[g][0] = acc[g][nt][rr * 2];
                v[g][1] = acc[g][nt][rr * 2 + 1];
                if (addb) { v[g][0] += Bias[g * 256 + j0]; v[g][1] += Bias[g * 256 + j0 + 1]; }
            }
            // h_old = hi + lo (precise reconstruction of carried state)
            const size_t zi = (size_t)M * 1024;
            float2 rh = __half22float2(*(const __half2*)&zr[zi + j0]);
            float2 rl = __half22float2(*(const __half2*)&zr[zi + 512 + j0]);
            float2 ch = __half22float2(*(const __half2*)&zr[zi + 256 + j0]);
            float2 cl = __half22float2(*(const __half2*)&zr[zi + 768 + j0]);
            float hro[2] = { rh.x + rl.x, rh.y + rl.y };
            float hco[2] = { ch.x + cl.x, ch.y + cl.y };
            float hr[2], hc[2];
#pragma unroll
            for (int jj = 0; jj < 2; ++jj) {
                float ur = sigmoidf_(v[0][jj]);
                float orr = sigmoidf_(v[1][jj]);
                float uc = sigmoidf_(v[2][jj]);
                float oc = sigmoidf_(v[3][jj]);
                float ir = tanhf(v[4][jj]);
                float ic = tanhf(v[5][jj]);
                hr[jj] = tanhf((1.0f - ur) * hro[jj] + ur * ir) * orr;
                hc[jj] = tanhf((1.0f - uc) * hco[jj] + uc * ic) * oc;
            }
            const int Mr = (((r + 1) & 31) << 6) | b;   // roll(h_col,+1,axis=0)
            uint32_t hrhi = hpack(hr[0], hr[1]);
            float r0f = hr[0] - __half2float(__float2half_rn(hr[0]));
            float r1f = hr[1] - __half2float(__float2half_rn(hr[1]));
            uint32_t hrlo = hpack(r0f, r1f);
            uint32_t hchi = hpack(hc[0], hc[1]);
            float c0f = hc[0] - __half2float(__float2half_rn(hc[0]));
            float c1f = hc[1] - __half2float(__float2half_rn(hc[1]));
            uint32_t hclo = hpack(c0f, c1f);

            *(uint32_t*)&zw[(size_t)M * 1024 + j0] = hrhi;
            *(uint32_t*)&zw[(size_t)M * 1024 + 512 + j0] = hrlo;
            *(uint32_t*)&zw[(size_t)Mr * 1024 + 256 + j0] = hchi;
            *(uint32_t*)&zw[(size_t)Mr * 1024 + 768 + j0] = hclo;

            if (layer == 0) {
                // layer-1 x input (hi only)
                const size_t xb = ((size_t)t * MTOT + M) * 512;
                *(uint32_t*)&g_x1[xb + j0] = hrhi;
                *(uint32_t*)&g_x1[xb + 256 + j0] = hchi;
            } else {
                const size_t ob = ((size_t)M * LLEN + t) * 512;
                *(float2*)&dout[ob + j0] = make_float2(hr[0], hr[1]);
                *(float2*)&dout[ob + 256 + j0] = make_float2(hc[0], hc[1]);
            }
            if (t >= RR - 1) {
                const int k = t - (RR - 1);
                if (r == k)
                    *(float2*)&dout[OFF1 + (((size_t)b * 2 + layer) * RR + k) * HH + j0] =
                        make_float2(hr[0], hr[1]);
                if (r == RR - 1)
                    *(float2*)&dout[OFF2 + (((size_t)b * 2 + layer) * RR + k) * HH + j0] =
                        make_float2(hc[0], hc[1]);
            }
        }
    }
}

// ---------------- host ----------------
extern "C" void kernel_launch(void* const* d_in, const int* in_sizes, int n_in,
                              void* d_out, int out_size) {
    (void)in_sizes; (void)n_in; (void)out_size;
    const float* inp  = (const float*)d_in[0];
    const float* Wf   = (const float*)d_in[1];
    const float* Wo   = (const float*)d_in[2];
    const float* Bias = (const float*)d_in[3];
    float* out = (float*)d_out;

    cudaFuncSetAttribute(gemm_k, cudaFuncAttributeMaxDynamicSharedMemorySize, SMEMT);

    prep_w<<<512, 256>>>(Wf, Wo);
    prep_x0<<<1024, 256>>>(inp);
    init_all<<<(MTOT * 1024 + 255) / 256, 256>>>();

    // wavefront: round s = layer0 step s | layer1 step s-1
    dim3 wgrid(MTOT / BM, HH / BJ, 2);       // 16 x 16 x 2
    for (int s = 0; s <= 63; ++s)
        gemm_k<<<wgrid, 256, SMEMT>>>(s, Bias, out);
}